// round 2
// baseline (speedup 1.0000x reference)
#include <cuda_runtime.h>
#include <cuda_bf16.h>

#define BN   2048
#define HID  128
#define MID  128
#define INN  32
#define OUTN 32
#define NSEG 63

// ---------------- scratch (device globals: no allocation allowed) ----------
__device__ float g_z[BN * HID];
__device__ float g_hact[BN * MID];
__device__ float g_k[BN * HID];
__device__ float g_kacc[BN * HID];
__device__ float g_y[BN * OUTN];

// Accurate cheap tanh: 2 MUFU (EX2 + RCP) + few FMAs, ~1e-6 rel err.
__device__ __forceinline__ float fast_tanh(float x) {
    float ax = fabsf(x);
    float e  = __expf(-2.0f * ax);                 // in (0,1]
    float r  = __fdividef(1.0f - e, 1.0f + e);     // tanh(|x|)
    return copysignf(r, x);
}

// ---------------- init: z0 = a[:,0] @ W_init + b_init ----------------------
__global__ void k_init(const float* __restrict__ coeffs,
                       const float* __restrict__ W_init,
                       const float* __restrict__ b_init) {
    int idx = blockIdx.x * blockDim.x + threadIdx.x;   // BN*HID
    int b = idx >> 7;
    int c = idx & 127;
    const float* a0 = coeffs + (long)b * NSEG * 128;   // a = first 32 of seg 0
    float acc = b_init[c];
#pragma unroll
    for (int i = 0; i < INN; i++) acc += a0[i] * W_init[i * HID + c];
    g_z[idx] = acc;
}

// ---------------- stage A: hact = relu((z + alpha*k_prev) @ W1 + b1) -------
__global__ void __launch_bounds__(128) k_fieldA(const float* __restrict__ W1,
                                                const float* __restrict__ b1,
                                                float alpha) {
    __shared__ float zs[16][128];
    int b0  = blockIdx.x * 16;
    int tid = threadIdx.x;
#pragma unroll
    for (int q = 0; q < 16; q++) {
        int r = q, m = tid;
        float v = g_z[(b0 + r) * 128 + m];
        if (alpha != 0.0f) v += alpha * g_k[(b0 + r) * 128 + m];
        zs[r][m] = v;
    }
    __syncthreads();
    int c = tid;
    float acc[16];
#pragma unroll
    for (int r = 0; r < 16; r++) acc[r] = 0.0f;
    for (int k = 0; k < 128; k++) {
        float w = W1[k * 128 + c];
#pragma unroll
        for (int r = 0; r < 16; r++) acc[r] += zs[r][k] * w;
    }
    float bb = b1[c];
#pragma unroll
    for (int r = 0; r < 16; r++)
        g_hact[(b0 + r) * 128 + c] = fmaxf(acc[r] + bb, 0.0f);
}

// ---------------- stage B: k = sum_i tanh(hact@W2 + b2) * dX ---------------
// CTA tile: 32 batch rows x 512 G-cols (= 16 output h dims). Grid (64, 8).
#define BT 32
#define CT 512
#define KC 8
__global__ void __launch_bounds__(256, 2) k_fieldB(const float* __restrict__ W2,
                                                   const float* __restrict__ b2,
                                                   const float* __restrict__ coeffs,
                                                   int seg, float wb, float wc, float wd,
                                                   int stage) {
    __shared__ float hs[128][33];       // hact transposed [m][row], padded
    __shared__ float w2s[KC][CT];
    __shared__ float dXs[BT][INN];
    __shared__ float b2s[CT];

    int tid  = threadIdx.x;
    int b0   = blockIdx.x * BT;
    int col0 = blockIdx.y * CT;

    // load hact tile (transposed into smem)
#pragma unroll
    for (int q = 0; q < 16; q++) {
        int idx = tid + 256 * q;        // 4096
        int r = idx >> 7, m = idx & 127;
        hs[m][r] = g_hact[(b0 + r) * 128 + m];
    }
    // dX = wb*b + wc*c + wd*d at segment `seg`
#pragma unroll
    for (int q = 0; q < 4; q++) {
        int idx = tid + 256 * q;        // 1024
        int r = idx >> 5, i = idx & 31;
        const float* cf = coeffs + ((long)(b0 + r) * NSEG + seg) * 128;
        dXs[r][i] = wb * cf[32 + i] + wc * cf[64 + i] + wd * cf[96 + i];
    }
#pragma unroll
    for (int q = 0; q < 2; q++) b2s[tid + 256 * q] = b2[col0 + tid + 256 * q];

    int tr = tid >> 5;                  // 0..7  -> rows tr*4 .. tr*4+3
    int tc = tid & 31;                  // 0..31 -> cols tc*16 .. tc*16+15
    float acc[4][16];
#pragma unroll
    for (int r = 0; r < 4; r++)
#pragma unroll
        for (int j = 0; j < 16; j++) acc[r][j] = 0.0f;

    for (int kc = 0; kc < 128; kc += KC) {
        __syncthreads();                // protect smem reuse (and initial fills)
#pragma unroll
        for (int q = 0; q < 4; q++) {
            int idx4 = tid + 256 * q;   // 1024 float4
            int rr = idx4 >> 7, pos = idx4 & 127;
            *(float4*)&w2s[rr][pos * 4] =
                *(const float4*)&W2[(long)(kc + rr) * 4096 + col0 + pos * 4];
        }
        __syncthreads();
#pragma unroll
        for (int k8 = 0; k8 < KC; k8++) {
            int k = kc + k8;
            float a0 = hs[k][tr * 4 + 0];
            float a1 = hs[k][tr * 4 + 1];
            float a2 = hs[k][tr * 4 + 2];
            float a3 = hs[k][tr * 4 + 3];
            const float4* wv = (const float4*)&w2s[k8][tc * 16];
#pragma unroll
            for (int j4 = 0; j4 < 4; j4++) {
                float4 w = wv[j4];
                acc[0][j4 * 4 + 0] += a0 * w.x; acc[0][j4 * 4 + 1] += a0 * w.y;
                acc[0][j4 * 4 + 2] += a0 * w.z; acc[0][j4 * 4 + 3] += a0 * w.w;
                acc[1][j4 * 4 + 0] += a1 * w.x; acc[1][j4 * 4 + 1] += a1 * w.y;
                acc[1][j4 * 4 + 2] += a1 * w.z; acc[1][j4 * 4 + 3] += a1 * w.w;
                acc[2][j4 * 4 + 0] += a2 * w.x; acc[2][j4 * 4 + 1] += a2 * w.y;
                acc[2][j4 * 4 + 2] += a2 * w.z; acc[2][j4 * 4 + 3] += a2 * w.w;
                acc[3][j4 * 4 + 0] += a3 * w.x; acc[3][j4 * 4 + 1] += a3 * w.y;
                acc[3][j4 * 4 + 2] += a3 * w.z; acc[3][j4 * 4 + 3] += a3 * w.w;
            }
        }
    }

    // epilogue: bias + tanh + contract over i, then RK4 bookkeeping
    float part[4] = {0.f, 0.f, 0.f, 0.f};
    int ibase = (tc & 1) * 16;
#pragma unroll
    for (int j = 0; j < 16; j++) {
        float bb = b2s[tc * 16 + j];
        int i = ibase + j;
#pragma unroll
        for (int r = 0; r < 4; r++) {
            float t = fast_tanh(acc[r][j] + bb);
            part[r] += t * dXs[tr * 4 + r][i];
        }
    }
#pragma unroll
    for (int r = 0; r < 4; r++)
        part[r] += __shfl_xor_sync(0xffffffffu, part[r], 1);

    if ((tc & 1) == 0) {
        int h = (col0 >> 5) + (tc >> 1);        // global output h dim
#pragma unroll
        for (int r = 0; r < 4; r++) {
            int idx = (b0 + tr * 4 + r) * 128 + h;
            float kv = part[r];
            if (stage == 0)      { g_k[idx] = kv; g_kacc[idx] = kv; }
            else if (stage == 3) { g_z[idx] += (g_kacc[idx] + kv) * (1.0f / 6.0f); }
            else                 { g_k[idx] = kv; g_kacc[idx] += 2.0f * kv; }
        }
    }
}

// ---------------- readout: y = zT @ W_ro + b_ro ----------------------------
__global__ void k_readout(const float* __restrict__ W_ro,
                          const float* __restrict__ b_ro) {
    int idx = blockIdx.x * blockDim.x + threadIdx.x;  // BN*32
    int b = idx >> 5, o = idx & 31;
    const float* zr = g_z + b * 128;
    float acc = b_ro[o];
#pragma unroll
    for (int h = 0; h < 128; h++) acc += zr[h] * W_ro[h * 32 + o];
    g_y[idx] = acc;
}

// ---------------- evolve: 10 RK4 steps of ev(y)=tanh(y@We1+be1)@We2+be2 ----
__global__ void __launch_bounds__(256) k_evolve(const float* __restrict__ We1,
                                                const float* __restrict__ be1,
                                                const float* __restrict__ We2,
                                                const float* __restrict__ be2,
                                                float* __restrict__ out) {
    __shared__ float w1s[INN * HID];    // 32x128
    __shared__ float w2s[HID * INN];    // 128x32
    __shared__ float ys[8][32];
    __shared__ float hsv[8][128];
    int tid = threadIdx.x;
    for (int i = tid; i < INN * HID; i += 256) w1s[i] = We1[i];
    for (int i = tid; i < HID * INN; i += 256) w2s[i] = We2[i];
    __syncthreads();

    int r = tid >> 5, lane = tid & 31;
    int b = blockIdx.x * 8 + r;
    float y = g_y[b * 32 + lane];
    float be1r[4];
#pragma unroll
    for (int k = 0; k < 4; k++) be1r[k] = be1[k * 32 + lane];
    float be2r = be2[lane];

    const float hstep = 0.5f;           // EVOLVE/ODE_STEPS = 5/10

    auto ev = [&](float yin) -> float {
        ys[r][lane] = yin;
        __syncwarp();
        float h0 = be1r[0], h1 = be1r[1], h2 = be1r[2], h3 = be1r[3];
#pragma unroll
        for (int i = 0; i < 32; i++) {
            float yi = ys[r][i];
            h0 += yi * w1s[i * 128 + lane];
            h1 += yi * w1s[i * 128 + 32 + lane];
            h2 += yi * w1s[i * 128 + 64 + lane];
            h3 += yi * w1s[i * 128 + 96 + lane];
        }
        hsv[r][lane]      = fast_tanh(h0);
        hsv[r][lane + 32] = fast_tanh(h1);
        hsv[r][lane + 64] = fast_tanh(h2);
        hsv[r][lane + 96] = fast_tanh(h3);
        __syncwarp();
        float o = be2r;
#pragma unroll
        for (int j = 0; j < 128; j++) o += hsv[r][j] * w2s[j * 32 + lane];
        __syncwarp();
        return o;
    };

    for (int s = 0; s < 10; s++) {
        float k1 = ev(y);
        float k2 = ev(y + 0.25f * k1);
        float k3 = ev(y + 0.25f * k2);
        float k4 = ev(y + 0.5f  * k3);
        y += (hstep / 6.0f) * (k1 + 2.0f * k2 + 2.0f * k3 + k4);
    }
    out[b * 32 + lane] = y;
}

// ---------------- host ------------------------------------------------------
extern "C" void kernel_launch(void* const* d_in, const int* in_sizes, int n_in,
                              void* d_out, int out_size) {
    const float* coeffs = (const float*)d_in[0];
    const float* W_init = (const float*)d_in[1];
    const float* b_init = (const float*)d_in[2];
    const float* W1     = (const float*)d_in[3];
    const float* b1     = (const float*)d_in[4];
    const float* W2     = (const float*)d_in[5];
    const float* b2     = (const float*)d_in[6];
    const float* W_ro   = (const float*)d_in[7];
    const float* b_ro   = (const float*)d_in[8];
    const float* We1    = (const float*)d_in[9];
    const float* be1    = (const float*)d_in[10];
    const float* We2    = (const float*)d_in[11];
    const float* be2    = (const float*)d_in[12];
    float* out = (float*)d_out;

    k_init<<<(BN * HID) / 256, 256>>>(coeffs, W_init, b_init);

    dim3 gB(BN / BT, 4096 / CT);   // (64, 8)
    for (int s = 0; s < NSEG; s++) {
        // k1: fr=0, seg=s
        k_fieldA<<<BN / 16, 128>>>(W1, b1, 0.0f);
        k_fieldB<<<gB, 256>>>(W2, b2, coeffs, s, 1.0f, 0.0f, 0.0f, 0);
        // k2: fr=0.5, seg=s
        k_fieldA<<<BN / 16, 128>>>(W1, b1, 0.5f);
        k_fieldB<<<gB, 256>>>(W2, b2, coeffs, s, 1.0f, 1.0f, 0.75f, 1);
        // k3: fr=0.5, seg=s
        k_fieldA<<<BN / 16, 128>>>(W1, b1, 0.5f);
        k_fieldB<<<gB, 256>>>(W2, b2, coeffs, s, 1.0f, 1.0f, 0.75f, 2);
        // k4: t+1 -> seg=s+1 fr=0, except s=62 -> seg=62 fr=1
        k_fieldA<<<BN / 16, 128>>>(W1, b1, 1.0f);
        int   seg4 = (s < NSEG - 1) ? s + 1 : NSEG - 1;
        float wc4  = (s < NSEG - 1) ? 0.0f : 2.0f;
        float wd4  = (s < NSEG - 1) ? 0.0f : 3.0f;
        k_fieldB<<<gB, 256>>>(W2, b2, coeffs, seg4, 1.0f, wc4, wd4, 3);
    }

    k_readout<<<(BN * OUTN) / 256, 256>>>(W_ro, b_ro);
    k_evolve<<<BN / 8, 256>>>(We1, be1, We2, be2, out);
}

// round 3
// speedup vs baseline: 2.4985x; 2.4985x over previous
#include <cuda_runtime.h>
#include <cuda_bf16.h>

#define BN   2048
#define HID  128
#define MIDN 128
#define INN  32
#define OUTN 32
#define NSEG 63

typedef unsigned long long ull;

__device__ float g_zbuf[2][BN * HID];
__device__ float g_kbuf[2][BN * HID];
__device__ float g_kacc[BN * HID];
__device__ float g_y[BN * OUTN];

__device__ __forceinline__ float fast_tanh(float x) {
    float ax = fabsf(x);
    float e  = __expf(-2.0f * ax);
    float r  = __fdividef(1.0f - e, 1.0f + e);
    return copysignf(r, x);
}
__device__ __forceinline__ ull pack2(float lo, float hi) {
    ull r; asm("mov.b64 %0, {%1, %2};" : "=l"(r) : "f"(lo), "f"(hi)); return r;
}
__device__ __forceinline__ void unpack2(ull v, float& lo, float& hi) {
    asm("mov.b64 {%0, %1}, %2;" : "=f"(lo), "=f"(hi) : "l"(v));
}
__device__ __forceinline__ ull ffma2(ull a, ull b, ull c) {
    ull d; asm("fma.rn.f32x2 %0, %1, %2, %3;" : "=l"(d) : "l"(a), "l"(b), "l"(c));
    return d;
}
__device__ __forceinline__ void cp16(void* sdst, const void* gsrc) {
    unsigned s = (unsigned)__cvta_generic_to_shared(sdst);
    asm volatile("cp.async.cg.shared.global [%0], [%1], 16;" :: "r"(s), "l"(gsrc));
}
#define CP_COMMIT() asm volatile("cp.async.commit_group;" ::: "memory")
#define CP_WAIT0()  asm volatile("cp.async.wait_group 0;"  ::: "memory")

// ---------------- init ------------------------------------------------------
__global__ void k_init(const float* __restrict__ coeffs,
                       const float* __restrict__ W_init,
                       const float* __restrict__ b_init) {
    int idx = blockIdx.x * blockDim.x + threadIdx.x;
    int b = idx >> 7;
    int c = idx & 127;
    const float* a0 = coeffs + (long)b * NSEG * 128;
    float acc = b_init[c];
#pragma unroll
    for (int i = 0; i < INN; i++) acc += a0[i] * W_init[i * HID + c];
    g_zbuf[0][idx] = acc;
}

// ---------------- fused RK4 stage kernel -----------------------------------
#define ROWS 32
#define TPB  256
#define KC   8
#define CCH  512
#define NCH  4
#define SMEM_BYTES (2*KC*CCH*4 + 128*34*4 + ROWS*INN*4)

__global__ void __launch_bounds__(TPB, 1) k_stage(
    const float* __restrict__ W1, const float* __restrict__ b1,
    const float* __restrict__ W2, const float* __restrict__ b2,
    const float* __restrict__ coeffs,
    int seg, float wb, float wc, float wd, float alpha, int stage, int zflip)
{
    extern __shared__ __align__(16) char sm[];
    float* w2s = (float*)sm;                               // [2][KC][CCH]
    float* hsm = (float*)(sm + 2*KC*CCH*4);                // [128][34]
    float* dxs = (float*)(sm + 2*KC*CCH*4 + 128*34*4);     // [32][32]
    float* zs  = w2s;                                      // alias buf0

    const int tid     = threadIdx.x;
    const int b0      = blockIdx.x * ROWS;
    const int colg0b  = blockIdx.y * 2048;

    const float* zin  = g_zbuf[zflip];
    float*       zout = g_zbuf[zflip ^ 1];
    const float* kin  = (stage == 2) ? g_kbuf[1] : g_kbuf[0];
    float*       kout = (stage == 1) ? g_kbuf[1] : g_kbuf[0];

    // zin = z + alpha*k_prev
#pragma unroll
    for (int q = 0; q < 4; q++) {
        int i4 = tid + TPB * q;
        int r = i4 >> 5, m4 = i4 & 31;
        float4 v = *(const float4*)&zin[(b0 + r) * 128 + m4 * 4];
        if (stage != 0) {
            float4 kv = *(const float4*)&kin[(b0 + r) * 128 + m4 * 4];
            v.x += alpha * kv.x; v.y += alpha * kv.y;
            v.z += alpha * kv.z; v.w += alpha * kv.w;
        }
        *(float4*)&zs[r * 128 + m4 * 4] = v;
    }
#pragma unroll
    for (int q = 0; q < 4; q++) {
        int idx = tid + TPB * q;
        int r = idx >> 5, i = idx & 31;
        const float* cf = coeffs + ((long)(b0 + r) * NSEG + seg) * 128;
        dxs[r * 32 + i] = wb * cf[32 + i] + wc * cf[64 + i] + wd * cf[96 + i];
    }
    __syncthreads();

    // GEMM1: hsm[mid][row] = relu(zin @ W1 + b1)
    {
        int c = tid & 127, half = tid >> 7;
        float a16[16];
#pragma unroll
        for (int r = 0; r < 16; r++) a16[r] = 0.0f;
        for (int k4 = 0; k4 < 128; k4 += 4) {
            float w0  = W1[(k4 + 0) * 128 + c];
            float w1v = W1[(k4 + 1) * 128 + c];
            float w2v = W1[(k4 + 2) * 128 + c];
            float w3v = W1[(k4 + 3) * 128 + c];
#pragma unroll
            for (int r = 0; r < 16; r++) {
                float4 zv = *(const float4*)&zs[(half * 16 + r) * 128 + k4];
                a16[r] = fmaf(zv.x, w0, fmaf(zv.y, w1v, fmaf(zv.z, w2v, fmaf(zv.w, w3v, a16[r]))));
            }
        }
        float bb1 = b1[c];
#pragma unroll
        for (int r = 0; r < 16; r++)
            hsm[c * 34 + half * 16 + r] = fmaxf(a16[r] + bb1, 0.0f);
    }
    __syncthreads();   // hsm ready; zs (buf0) now free

    const int tc = tid & 127;
    const int th = tid >> 7;
    const int ib = (tc & 7) * 4;

    for (int ch = 0; ch < NCH; ch++) {
        const int colg0 = colg0b + ch * CCH;

        // prefetch kc=0 into buf0
#pragma unroll
        for (int q = 0; q < 4; q++) {
            int i4 = tid + TPB * q;
            int rr = i4 >> 7, pp = i4 & 127;
            cp16(&w2s[rr * CCH + pp * 4], &W2[rr * 4096 + colg0 + pp * 4]);
        }
        CP_COMMIT();

        ull acc[8][4];
#pragma unroll
        for (int p = 0; p < 8; p++)
#pragma unroll
            for (int j = 0; j < 4; j++) acc[p][j] = 0ull;

        for (int kcb = 0; kcb < 16; kcb++) {
            const int kc = kcb * KC;
            const int cur = kcb & 1;
            CP_WAIT0();
            __syncthreads();
            if (kcb < 15) {
                float* nbuf = w2s + (cur ^ 1) * KC * CCH;
#pragma unroll
                for (int q = 0; q < 4; q++) {
                    int i4 = tid + TPB * q;
                    int rr = i4 >> 7, pp = i4 & 127;
                    cp16(&nbuf[rr * CCH + pp * 4],
                         &W2[(kc + KC + rr) * 4096 + colg0 + pp * 4]);
                }
                CP_COMMIT();
            }
            const float* cbuf = w2s + cur * KC * CCH;
#pragma unroll
            for (int kk = 0; kk < KC; kk++) {
                const float* hrow = &hsm[(kc + kk) * 34 + th * 16];
                ull ap[8];
#pragma unroll
                for (int p = 0; p < 8; p++) ap[p] = *(const ull*)(hrow + 2 * p);
                float4 wv = *(const float4*)&cbuf[kk * CCH + tc * 4];
                ull w0  = pack2(wv.x, wv.x), w1d = pack2(wv.y, wv.y);
                ull w2d = pack2(wv.z, wv.z), w3d = pack2(wv.w, wv.w);
#pragma unroll
                for (int p = 0; p < 8; p++) {
                    acc[p][0] = ffma2(ap[p], w0,  acc[p][0]);
                    acc[p][1] = ffma2(ap[p], w1d, acc[p][1]);
                    acc[p][2] = ffma2(ap[p], w2d, acc[p][2]);
                    acc[p][3] = ffma2(ap[p], w3d, acc[p][3]);
                }
            }
        }

        // epilogue
        float part[16];
#pragma unroll
        for (int r = 0; r < 16; r++) part[r] = 0.0f;
        float4 bv = __ldg((const float4*)&b2[colg0 + tc * 4]);
        float bb[4] = {bv.x, bv.y, bv.z, bv.w};
#pragma unroll
        for (int j = 0; j < 4; j++) {
#pragma unroll
            for (int p = 0; p < 8; p++) {
                float lo, hi; unpack2(acc[p][j], lo, hi);
                float t0 = fast_tanh(lo + bb[j]);
                float t1 = fast_tanh(hi + bb[j]);
                part[2 * p]     += t0 * dxs[(th * 16 + 2 * p) * 32 + ib + j];
                part[2 * p + 1] += t1 * dxs[(th * 16 + 2 * p + 1) * 32 + ib + j];
            }
        }
#pragma unroll
        for (int r = 0; r < 16; r++) {
            part[r] += __shfl_xor_sync(0xffffffffu, part[r], 1);
            part[r] += __shfl_xor_sync(0xffffffffu, part[r], 2);
            part[r] += __shfl_xor_sync(0xffffffffu, part[r], 4);
        }
        if ((tc & 7) == 0) {
            int h = (colg0 >> 5) + (tc >> 3);
#pragma unroll
            for (int r = 0; r < 16; r++) {
                int idx = (b0 + th * 16 + r) * 128 + h;
                float kv = part[r];
                if (stage == 0)      { kout[idx] = kv; g_kacc[idx] = kv; }
                else if (stage == 3) { zout[idx] = zin[idx] + (g_kacc[idx] + kv) * (1.0f / 6.0f); }
                else                 { kout[idx] = kv; g_kacc[idx] += 2.0f * kv; }
            }
        }
    }
}

// ---------------- readout ---------------------------------------------------
__global__ void k_readout(const float* __restrict__ W_ro,
                          const float* __restrict__ b_ro) {
    int idx = blockIdx.x * blockDim.x + threadIdx.x;
    int b = idx >> 5, o = idx & 31;
    const float* zr = g_zbuf[1] + b * 128;   // NSEG odd -> final z in buf 1
    float acc = b_ro[o];
#pragma unroll
    for (int h = 0; h < 128; h++) acc += zr[h] * W_ro[h * 32 + o];
    g_y[idx] = acc;
}

// ---------------- evolve ----------------------------------------------------
__global__ void __launch_bounds__(256) k_evolve(const float* __restrict__ We1,
                                                const float* __restrict__ be1,
                                                const float* __restrict__ We2,
                                                const float* __restrict__ be2,
                                                float* __restrict__ out) {
    __shared__ float w1s[INN * HID];
    __shared__ float w2sE[HID * INN];
    __shared__ float ys[8][32];
    __shared__ float hsv[8][128];
    int tid = threadIdx.x;
    for (int i = tid; i < INN * HID; i += 256) w1s[i] = We1[i];
    for (int i = tid; i < HID * INN; i += 256) w2sE[i] = We2[i];
    __syncthreads();

    int r = tid >> 5, lane = tid & 31;
    int b = blockIdx.x * 8 + r;
    float y = g_y[b * 32 + lane];
    float be1r[4];
#pragma unroll
    for (int k = 0; k < 4; k++) be1r[k] = be1[k * 32 + lane];
    float be2r = be2[lane];
    const float hstep = 0.5f;

    auto ev = [&](float yin) -> float {
        ys[r][lane] = yin;
        __syncwarp();
        float h0 = be1r[0], h1 = be1r[1], h2 = be1r[2], h3 = be1r[3];
#pragma unroll
        for (int i = 0; i < 32; i++) {
            float yi = ys[r][i];
            h0 += yi * w1s[i * 128 + lane];
            h1 += yi * w1s[i * 128 + 32 + lane];
            h2 += yi * w1s[i * 128 + 64 + lane];
            h3 += yi * w1s[i * 128 + 96 + lane];
        }
        hsv[r][lane]      = fast_tanh(h0);
        hsv[r][lane + 32] = fast_tanh(h1);
        hsv[r][lane + 64] = fast_tanh(h2);
        hsv[r][lane + 96] = fast_tanh(h3);
        __syncwarp();
        float o = be2r;
#pragma unroll
        for (int j = 0; j < 128; j++) o += hsv[r][j] * w2sE[j * 32 + lane];
        __syncwarp();
        return o;
    };

    for (int s = 0; s < 10; s++) {
        float k1 = ev(y);
        float k2 = ev(y + 0.25f * k1);
        float k3 = ev(y + 0.25f * k2);
        float k4 = ev(y + 0.5f  * k3);
        y += (hstep / 6.0f) * (k1 + 2.0f * k2 + 2.0f * k3 + k4);
    }
    out[b * 32 + lane] = y;
}

// ---------------- host ------------------------------------------------------
extern "C" void kernel_launch(void* const* d_in, const int* in_sizes, int n_in,
                              void* d_out, int out_size) {
    const float* coeffs = (const float*)d_in[0];
    const float* W_init = (const float*)d_in[1];
    const float* b_init = (const float*)d_in[2];
    const float* W1     = (const float*)d_in[3];
    const float* b1     = (const float*)d_in[4];
    const float* W2     = (const float*)d_in[5];
    const float* b2     = (const float*)d_in[6];
    const float* W_ro   = (const float*)d_in[7];
    const float* b_ro   = (const float*)d_in[8];
    const float* We1    = (const float*)d_in[9];
    const float* be1    = (const float*)d_in[10];
    const float* We2    = (const float*)d_in[11];
    const float* be2    = (const float*)d_in[12];
    float* out = (float*)d_out;

    cudaFuncSetAttribute(k_stage, cudaFuncAttributeMaxDynamicSharedMemorySize, SMEM_BYTES);

    k_init<<<(BN * HID) / 256, 256>>>(coeffs, W_init, b_init);

    dim3 g(BN / ROWS, 2);
    for (int s = 0; s < NSEG; s++) {
        int zf = s & 1;
        k_stage<<<g, TPB, SMEM_BYTES>>>(W1, b1, W2, b2, coeffs, s, 1.0f, 0.0f, 0.0f, 0.0f, 0, zf);
        k_stage<<<g, TPB, SMEM_BYTES>>>(W1, b1, W2, b2, coeffs, s, 1.0f, 1.0f, 0.75f, 0.5f, 1, zf);
        k_stage<<<g, TPB, SMEM_BYTES>>>(W1, b1, W2, b2, coeffs, s, 1.0f, 1.0f, 0.75f, 0.5f, 2, zf);
        int   seg4 = (s < NSEG - 1) ? s + 1 : NSEG - 1;
        float wc4  = (s < NSEG - 1) ? 0.0f : 2.0f;
        float wd4  = (s < NSEG - 1) ? 0.0f : 3.0f;
        k_stage<<<g, TPB, SMEM_BYTES>>>(W1, b1, W2, b2, coeffs, seg4, 1.0f, wc4, wd4, 1.0f, 3, zf);
    }

    k_readout<<<(BN * OUTN) / 256, 256>>>(W_ro, b_ro);
    k_evolve<<<BN / 8, 256>>>(We1, be1, We2, be2, out);
}

// round 5
// speedup vs baseline: 2.6394x; 1.0564x over previous
#include <cuda_runtime.h>
#include <cuda_bf16.h>

#define BN   2048
#define HID  128
#define MIDN 128
#define INN  32
#define OUTN 32
#define NSEG 63

typedef unsigned long long ull;

__device__ float g_zbuf[2][BN * HID];
__device__ float g_kbuf[2][BN * HID];
__device__ float g_kacc[BN * HID];
__device__ float g_y[BN * OUTN];

__device__ __forceinline__ float fast_tanh(float x) {
    float ax = fabsf(x);
    float e  = __expf(-2.0f * ax);
    float r  = __fdividef(1.0f - e, 1.0f + e);
    return copysignf(r, x);
}
__device__ __forceinline__ ull pack2(float lo, float hi) {
    ull r; asm("mov.b64 %0, {%1, %2};" : "=l"(r) : "f"(lo), "f"(hi)); return r;
}
__device__ __forceinline__ void unpack2(ull v, float& lo, float& hi) {
    asm("mov.b64 {%0, %1}, %2;" : "=f"(lo), "=f"(hi) : "l"(v));
}
__device__ __forceinline__ ull ffma2(ull a, ull b, ull c) {
    ull d; asm("fma.rn.f32x2 %0, %1, %2, %3;" : "=l"(d) : "l"(a), "l"(b), "l"(c));
    return d;
}
__device__ __forceinline__ void cp16(void* sdst, const void* gsrc) {
    unsigned s = (unsigned)__cvta_generic_to_shared(sdst);
    asm volatile("cp.async.cg.shared.global [%0], [%1], 16;" :: "r"(s), "l"(gsrc));
}
#define CP_COMMIT() asm volatile("cp.async.commit_group;" ::: "memory")
#define CP_WAIT0()  asm volatile("cp.async.wait_group 0;"  ::: "memory")

// ---------------- init ------------------------------------------------------
__global__ void k_init(const float* __restrict__ coeffs,
                       const float* __restrict__ W_init,
                       const float* __restrict__ b_init) {
    int idx = blockIdx.x * blockDim.x + threadIdx.x;
    int b = idx >> 7;
    int c = idx & 127;
    const float* a0 = coeffs + (long)b * NSEG * 128;
    float acc = b_init[c];
#pragma unroll
    for (int i = 0; i < INN; i++) acc += a0[i] * W_init[i * HID + c];
    g_zbuf[0][idx] = acc;
}

// ---------------- fused RK4 stage kernel -----------------------------------
// Grid (64, 4): x = 32-row batch tile, y = 1024-col quarter of 4096 G-cols.
#define ROWS 32
#define TPB  256
#define KC   16
#define CCH  256
#define NCH  4
#define SMEM_BYTES (2*KC*CCH*4 /*32KB*/ + 128*34*4 /*17KB*/ + ROWS*INN*4 /*4KB*/)

__global__ void __launch_bounds__(TPB, 2) k_stage(
    const float* __restrict__ W1, const float* __restrict__ b1,
    const float* __restrict__ W2, const float* __restrict__ b2,
    const float* __restrict__ coeffs,
    int seg, float wb, float wc, float wd, float alpha, int stage, int zflip)
{
    extern __shared__ __align__(16) char sm[];
    float* w2s = (float*)sm;                               // [2][KC][CCH]
    float* hsm = (float*)(sm + 2*KC*CCH*4);                // [128][34]
    float* dxs = (float*)(sm + 2*KC*CCH*4 + 128*34*4);     // [32][32]
    float* zs  = w2s;                                      // alias bufs (16KB)

    const int tid    = threadIdx.x;
    const int b0     = blockIdx.x * ROWS;
    const int colq0  = blockIdx.y * (NCH * CCH);           // 1024-col quarter

    const float* zin  = g_zbuf[zflip];
    float*       zout = g_zbuf[zflip ^ 1];
    const float* kin  = (stage == 2) ? g_kbuf[1] : g_kbuf[0];
    float*       kout = (stage == 1) ? g_kbuf[1] : g_kbuf[0];

    // zin = z + alpha*k_prev into zs[32][128]
#pragma unroll
    for (int q = 0; q < 4; q++) {
        int i4 = tid + TPB * q;
        int r = i4 >> 5, m4 = i4 & 31;
        float4 v = *(const float4*)&zin[(b0 + r) * 128 + m4 * 4];
        if (stage != 0) {
            float4 kv = *(const float4*)&kin[(b0 + r) * 128 + m4 * 4];
            v.x += alpha * kv.x; v.y += alpha * kv.y;
            v.z += alpha * kv.z; v.w += alpha * kv.w;
        }
        *(float4*)&zs[r * 128 + m4 * 4] = v;
    }
#pragma unroll
    for (int q = 0; q < 4; q++) {
        int idx = tid + TPB * q;
        int r = idx >> 5, i = idx & 31;
        const float* cf = coeffs + ((long)(b0 + r) * NSEG + seg) * 128;
        dxs[r * 32 + i] = wb * cf[32 + i] + wc * cf[64 + i] + wd * cf[96 + i];
    }
    __syncthreads();

    // GEMM1: hsm[mid][row] = relu(zin @ W1 + b1)  (transposed, padded)
    {
        int c = tid & 127, half = tid >> 7;
        float a16[16];
#pragma unroll
        for (int r = 0; r < 16; r++) a16[r] = 0.0f;
        for (int k4 = 0; k4 < 128; k4 += 4) {
            float w0  = W1[(k4 + 0) * 128 + c];
            float w1v = W1[(k4 + 1) * 128 + c];
            float w2v = W1[(k4 + 2) * 128 + c];
            float w3v = W1[(k4 + 3) * 128 + c];
#pragma unroll
            for (int r = 0; r < 16; r++) {
                float4 zv = *(const float4*)&zs[(half * 16 + r) * 128 + k4];
                a16[r] = fmaf(zv.x, w0, fmaf(zv.y, w1v, fmaf(zv.z, w2v, fmaf(zv.w, w3v, a16[r]))));
            }
        }
        float bb1 = b1[c];
#pragma unroll
        for (int r = 0; r < 16; r++)
            hsm[c * 34 + half * 16 + r] = fmaxf(a16[r] + bb1, 0.0f);
    }
    __syncthreads();   // hsm ready; zs (w2s bufs) now free

    // thread tile: 8 rows (4 packed) x 4 cols
    const int tc = tid & 63;                // col group: cols tc*4..tc*4+3
    const int th = tid >> 6;                // row group: rows th*8..th*8+7
    const int ib = (tc & 7) * 4;            // i-base within h group

    for (int ch = 0; ch < NCH; ch++) {
        const int colg0 = colq0 + ch * CCH;

        // prefetch kc=0 into buf0: KC*CCH floats = 1024 float4, 4/thread
#pragma unroll
        for (int q = 0; q < 4; q++) {
            int i4 = tid + TPB * q;
            int rr = i4 >> 6, pp = i4 & 63;
            cp16(&w2s[rr * CCH + pp * 4], &W2[rr * 4096 + colg0 + pp * 4]);
        }
        CP_COMMIT();

        ull acc[4][4];
#pragma unroll
        for (int p = 0; p < 4; p++)
#pragma unroll
            for (int j = 0; j < 4; j++) acc[p][j] = 0ull;

        for (int kcb = 0; kcb < 128 / KC; kcb++) {
            const int kc = kcb * KC;
            const int cur = kcb & 1;
            CP_WAIT0();
            __syncthreads();
            if (kcb < 128 / KC - 1) {
                float* nbuf = w2s + (cur ^ 1) * KC * CCH;
#pragma unroll
                for (int q = 0; q < 4; q++) {
                    int i4 = tid + TPB * q;
                    int rr = i4 >> 6, pp = i4 & 63;
                    cp16(&nbuf[rr * CCH + pp * 4],
                         &W2[(kc + KC + rr) * 4096 + colg0 + pp * 4]);
                }
                CP_COMMIT();
            }
            const float* cbuf = w2s + cur * KC * CCH;
#pragma unroll
            for (int kk = 0; kk < KC; kk++) {
                const float* hrow = &hsm[(kc + kk) * 34 + th * 8];
                ull ap[4];
#pragma unroll
                for (int p = 0; p < 4; p++) ap[p] = *(const ull*)(hrow + 2 * p);
                float4 wv = *(const float4*)&cbuf[kk * CCH + tc * 4];
                ull w0  = pack2(wv.x, wv.x), w1d = pack2(wv.y, wv.y);
                ull w2d = pack2(wv.z, wv.z), w3d = pack2(wv.w, wv.w);
#pragma unroll
                for (int p = 0; p < 4; p++) {
                    acc[p][0] = ffma2(ap[p], w0,  acc[p][0]);
                    acc[p][1] = ffma2(ap[p], w1d, acc[p][1]);
                    acc[p][2] = ffma2(ap[p], w2d, acc[p][2]);
                    acc[p][3] = ffma2(ap[p], w3d, acc[p][3]);
                }
            }
        }

        // epilogue: bias + tanh + contract i, reduce over 8 lanes, RK4 write
        float part[8];
#pragma unroll
        for (int r = 0; r < 8; r++) part[r] = 0.0f;
        float4 bv = __ldg((const float4*)&b2[colg0 + tc * 4]);
        float bb[4] = {bv.x, bv.y, bv.z, bv.w};
#pragma unroll
        for (int j = 0; j < 4; j++) {
#pragma unroll
            for (int p = 0; p < 4; p++) {
                float lo, hi; unpack2(acc[p][j], lo, hi);
                float t0 = fast_tanh(lo + bb[j]);
                float t1 = fast_tanh(hi + bb[j]);
                part[2 * p]     += t0 * dxs[(th * 8 + 2 * p) * 32 + ib + j];
                part[2 * p + 1] += t1 * dxs[(th * 8 + 2 * p + 1) * 32 + ib + j];
            }
        }
#pragma unroll
        for (int r = 0; r < 8; r++) {
            part[r] += __shfl_xor_sync(0xffffffffu, part[r], 1);
            part[r] += __shfl_xor_sync(0xffffffffu, part[r], 2);
            part[r] += __shfl_xor_sync(0xffffffffu, part[r], 4);
        }
        if ((tc & 7) == 0) {
            int h = (colg0 >> 5) + (tc >> 3);
#pragma unroll
            for (int r = 0; r < 8; r++) {
                int idx = (b0 + th * 8 + r) * 128 + h;
                float kv = part[r];
                if (stage == 0)      { kout[idx] = kv; g_kacc[idx] = kv; }
                else if (stage == 3) { zout[idx] = zin[idx] + (g_kacc[idx] + kv) * (1.0f / 6.0f); }
                else                 { kout[idx] = kv; g_kacc[idx] += 2.0f * kv; }
            }
        }
    }
}

// ---------------- readout ---------------------------------------------------
__global__ void k_readout(const float* __restrict__ W_ro,
                          const float* __restrict__ b_ro) {
    int idx = blockIdx.x * blockDim.x + threadIdx.x;
    int b = idx >> 5, o = idx & 31;
    const float* zr = g_zbuf[1] + b * 128;   // NSEG odd -> final z in buf 1
    float acc = b_ro[o];
#pragma unroll
    for (int h = 0; h < 128; h++) acc += zr[h] * W_ro[h * 32 + o];
    g_y[idx] = acc;
}

// ---------------- evolve ----------------------------------------------------
__global__ void __launch_bounds__(256) k_evolve(const float* __restrict__ We1,
                                                const float* __restrict__ be1,
                                                const float* __restrict__ We2,
                                                const float* __restrict__ be2,
                                                float* __restrict__ out) {
    __shared__ float w1s[INN * HID];
    __shared__ float w2sE[HID * INN];
    __shared__ float ys[8][32];
    __shared__ float hsv[8][128];
    int tid = threadIdx.x;
    for (int i = tid; i < INN * HID; i += 256) w1s[i] = We1[i];
    for (int i = tid; i < HID * INN; i += 256) w2sE[i] = We2[i];
    __syncthreads();

    int r = tid >> 5, lane = tid & 31;
    int b = blockIdx.x * 8 + r;
    float y = g_y[b * 32 + lane];
    float be1r[4];
#pragma unroll
    for (int k = 0; k < 4; k++) be1r[k] = be1[k * 32 + lane];
    float be2r = be2[lane];
    const float hstep = 0.5f;

    auto ev = [&](float yin) -> float {
        ys[r][lane] = yin;
        __syncwarp();
        float h0 = be1r[0], h1 = be1r[1], h2 = be1r[2], h3 = be1r[3];
#pragma unroll
        for (int i = 0; i < 32; i++) {
            float yi = ys[r][i];
            h0 += yi * w1s[i * 128 + lane];
            h1 += yi * w1s[i * 128 + 32 + lane];
            h2 += yi * w1s[i * 128 + 64 + lane];
            h3 += yi * w1s[i * 128 + 96 + lane];
        }
        hsv[r][lane]      = fast_tanh(h0);
        hsv[r][lane + 32] = fast_tanh(h1);
        hsv[r][lane + 64] = fast_tanh(h2);
        hsv[r][lane + 96] = fast_tanh(h3);
        __syncwarp();
        float o = be2r;
#pragma unroll
        for (int j = 0; j < 128; j++) o += hsv[r][j] * w2sE[j * 32 + lane];
        __syncwarp();
        return o;
    };

    for (int s = 0; s < 10; s++) {
        float k1 = ev(y);
        float k2 = ev(y + 0.25f * k1);
        float k3 = ev(y + 0.25f * k2);
        float k4 = ev(y + 0.5f  * k3);
        y += (hstep / 6.0f) * (k1 + 2.0f * k2 + 2.0f * k3 + k4);
    }
    out[b * 32 + lane] = y;
}

// ---------------- host ------------------------------------------------------
extern "C" void kernel_launch(void* const* d_in, const int* in_sizes, int n_in,
                              void* d_out, int out_size) {
    const float* coeffs = (const float*)d_in[0];
    const float* W_init = (const float*)d_in[1];
    const float* b_init = (const float*)d_in[2];
    const float* W1     = (const float*)d_in[3];
    const float* b1     = (const float*)d_in[4];
    const float* W2     = (const float*)d_in[5];
    const float* b2     = (const float*)d_in[6];
    const float* W_ro   = (const float*)d_in[7];
    const float* b_ro   = (const float*)d_in[8];
    const float* We1    = (const float*)d_in[9];
    const float* be1    = (const float*)d_in[10];
    const float* We2    = (const float*)d_in[11];
    const float* be2    = (const float*)d_in[12];
    float* out = (float*)d_out;

    cudaFuncSetAttribute(k_stage, cudaFuncAttributeMaxDynamicSharedMemorySize, SMEM_BYTES);

    k_init<<<(BN * HID) / 256, 256>>>(coeffs, W_init, b_init);

    dim3 g(BN / ROWS, 4);   // 256 CTAs
    for (int s = 0; s < NSEG; s++) {
        int zf = s & 1;
        k_stage<<<g, TPB, SMEM_BYTES>>>(W1, b1, W2, b2, coeffs, s, 1.0f, 0.0f, 0.0f, 0.0f, 0, zf);
        k_stage<<<g, TPB, SMEM_BYTES>>>(W1, b1, W2, b2, coeffs, s, 1.0f, 1.0f, 0.75f, 0.5f, 1, zf);
        k_stage<<<g, TPB, SMEM_BYTES>>>(W1, b1, W2, b2, coeffs, s, 1.0f, 1.0f, 0.75f, 0.5f, 2, zf);
        int   seg4 = (s < NSEG - 1) ? s + 1 : NSEG - 1;
        float wc4  = (s < NSEG - 1) ? 0.0f : 2.0f;
        float wd4  = (s < NSEG - 1) ? 0.0f : 3.0f;
        k_stage<<<g, TPB, SMEM_BYTES>>>(W1, b1, W2, b2, coeffs, seg4, 1.0f, wc4, wd4, 1.0f, 3, zf);
    }

    k_readout<<<(BN * OUTN) / 256, 256>>>(W_ro, b_ro);
    k_evolve<<<BN / 8, 256>>>(We1, be1, We2, be2, out);
}

// round 10
// speedup vs baseline: 3.3933x; 1.2856x over previous
#include <cuda_runtime.h>
#include <cuda_bf16.h>
#include <stdint.h>

#define BN   2048
#define HID  128
#define INN  32
#define OUTN 32
#define NSEG 63

// ---------------- device scratch -------------------------------------------
__device__ float g_zbuf[2][BN * HID];
__device__ float g_kbuf[2][BN * HID];
__device__ float g_kacc[BN * HID];
__device__ float g_y[BN * OUTN];
__device__ __nv_bfloat16 g_h0[BN * HID];     // hact split 0, row-major [row][k]
__device__ __nv_bfloat16 g_h1[BN * HID];     // hact split 1
__device__ __nv_bfloat16 g_wf0[4096 * 128];  // W2 split 0, B-fragment order
__device__ __nv_bfloat16 g_wf1[4096 * 128];  // W2 split 1

// ---------------- helpers ---------------------------------------------------
__device__ __forceinline__ float fast_tanh(float x) {
    float ax = fabsf(x);
    float e  = __expf(-2.0f * ax);
    float r  = __fdividef(1.0f - e, 1.0f + e);
    return copysignf(r, x);
}
__device__ __forceinline__ void cp16(void* sdst, const void* gsrc) {
    unsigned s = (unsigned)__cvta_generic_to_shared(sdst);
    asm volatile("cp.async.cg.shared.global [%0], [%1], 16;" :: "r"(s), "l"(gsrc));
}
#define CP_COMMIT() asm volatile("cp.async.commit_group;" ::: "memory")
#define CP_WAIT0()  asm volatile("cp.async.wait_group 0;"  ::: "memory")

// mma.sync m16n8k16 row.col bf16 -> f32 (supported on plain sm_103 target)
__device__ __forceinline__ void mma16816(float* d, const uint32_t* a, const uint32_t* b) {
    asm volatile(
        "mma.sync.aligned.m16n8k16.row.col.f32.bf16.bf16.f32 "
        "{%0,%1,%2,%3}, {%4,%5,%6,%7}, {%8,%9}, {%0,%1,%2,%3};"
        : "+f"(d[0]), "+f"(d[1]), "+f"(d[2]), "+f"(d[3])
        : "r"(a[0]), "r"(a[1]), "r"(a[2]), "r"(a[3]), "r"(b[0]), "r"(b[1]));
}

// ---------------- one-time: W2 bf16 splits in B-fragment order --------------
// B tile for mma: 16(k) x 8(n), .col. Thread t: b0 = (k=(t&3)*2+{0,1}, n=t>>2),
// b1 = (k=(t&3)*2+8+{0,1}, n=t>>2). Layout: [ntile(512)][ktile(8)][lane(32)][4 bf16].
__global__ void k_prep(const float* __restrict__ W2) {
    int idx = blockIdx.x * 256 + threadIdx.x;   // 524288 = 128k * 4096n
    int k = idx >> 12;
    int n = idx & 4095;
    float w = W2[(long)k * 4096 + n];
    __nv_bfloat16 w0 = __float2bfloat16(w);
    __nv_bfloat16 w1 = __float2bfloat16(w - __bfloat162float(w0));
    int nt = n >> 3, kt = k >> 4;
    int t  = ((n & 7) << 2) | ((k >> 1) & 3);
    int r  = (k >> 3) & 1, hh = k & 1;
    uint32_t pos = ((uint32_t)((nt * 8 + kt) * 32 + t) << 2) + (r << 1) + hh;
    g_wf0[pos] = w0;
    g_wf1[pos] = w1;
}

// ---------------- init: z0 = a[:,0] @ W_init + b_init ----------------------
__global__ void k_init(const float* __restrict__ coeffs,
                       const float* __restrict__ W_init,
                       const float* __restrict__ b_init) {
    int idx = blockIdx.x * blockDim.x + threadIdx.x;
    int b = idx >> 7, c = idx & 127;
    const float* a0 = coeffs + (long)b * NSEG * 128;
    float acc = b_init[c];
#pragma unroll
    for (int i = 0; i < INN; i++) acc += a0[i] * W_init[i * HID + c];
    g_zbuf[0][idx] = acc;
}

// ---------------- per-stage: hact = relu((z+alpha*k)@W1+b1) -> bf16 splits -
__global__ void __launch_bounds__(256) k_hact(const float* __restrict__ W1,
                                              const float* __restrict__ b1,
                                              float alpha, int stage, int zflip) {
    __shared__ float zs[16 * 128];
    const int tid = threadIdx.x;
    const int b0  = blockIdx.x * 16;
    const float* zin = g_zbuf[zflip];
    const float* kin = (stage == 2) ? g_kbuf[1] : g_kbuf[0];

#pragma unroll
    for (int q = 0; q < 2; q++) {
        int i4 = tid + 256 * q;              // 512 float4
        int r = i4 >> 5, m4 = i4 & 31;
        float4 v = *(const float4*)&zin[(b0 + r) * 128 + m4 * 4];
        if (stage != 0) {
            float4 kv = *(const float4*)&kin[(b0 + r) * 128 + m4 * 4];
            v.x += alpha * kv.x; v.y += alpha * kv.y;
            v.z += alpha * kv.z; v.w += alpha * kv.w;
        }
        *(float4*)&zs[r * 128 + m4 * 4] = v;
    }
    __syncthreads();

    int c = tid & 127, half = tid >> 7;      // rows half*8 .. half*8+7
    float a8[8];
#pragma unroll
    for (int r = 0; r < 8; r++) a8[r] = 0.0f;
    for (int k4 = 0; k4 < 128; k4 += 4) {
        float w0  = W1[(k4 + 0) * 128 + c];
        float w1v = W1[(k4 + 1) * 128 + c];
        float w2v = W1[(k4 + 2) * 128 + c];
        float w3v = W1[(k4 + 3) * 128 + c];
#pragma unroll
        for (int r = 0; r < 8; r++) {
            float4 zv = *(const float4*)&zs[(half * 8 + r) * 128 + k4];
            a8[r] = fmaf(zv.x, w0, fmaf(zv.y, w1v, fmaf(zv.z, w2v, fmaf(zv.w, w3v, a8[r]))));
        }
    }
    float bb1 = b1[c];
#pragma unroll
    for (int r = 0; r < 8; r++) {
        int rowg = b0 + half * 8 + r;
        float h = fmaxf(a8[r] + bb1, 0.0f);
        __nv_bfloat16 h0 = __float2bfloat16(h);
        __nv_bfloat16 h1 = __float2bfloat16(h - __bfloat162float(h0));
        g_h0[rowg * 128 + c] = h0;
        g_h1[rowg * 128 + c] = h1;
    }
}

// ---------------- per-stage: HMMA GEMM2 + tanh + contraction + RK4 ---------
// CTA: 128 rows x 128 cols. 8 warps = 4(m) x 2(n). Warp tile: 32m x 64n.
// Grid (16, 32): x = row band, y = 128-col tile.
#define PADK  136                           // bf16 row stride (272B): conflict-free
#define SA0   0                             // 128*272 = 34816
#define SA1   34816                         // 34816
#define SDX   69632                         // dxT[32][128] f32 = 16384
#define SKST  86016                         // kst[128][4] f32 = 2048
#define SB2   88064                         // b2s[128] = 512
#define SMEMT 88576

__global__ void __launch_bounds__(256) k_gemm2(
    const float* __restrict__ b2, const float* __restrict__ coeffs,
    int seg, float wb, float wc, float wd, int stage, int zflip)
{
    extern __shared__ __align__(16) char sm[];
    __nv_bfloat16* a0s = (__nv_bfloat16*)(sm + SA0);
    __nv_bfloat16* a1s = (__nv_bfloat16*)(sm + SA1);
    float* dxT = (float*)(sm + SDX);        // [i][row]
    float* kst = (float*)(sm + SKST);       // [row][4]
    float* b2s = (float*)(sm + SB2);

    const int tid  = threadIdx.x;
    const int band = blockIdx.x;            // 0..15
    const int ct   = blockIdx.y;            // 0..31
    const int lane = tid & 31, wid = tid >> 5;
    const int wm = wid & 3, wn = wid >> 2;
    const int g = lane >> 2, tq = lane & 3;

    // ---- stage A splits into padded smem (cp.async) ----
    {
        const char* s0 = (const char*)g_h0 + (size_t)(band * 128) * 256;
        const char* s1 = (const char*)g_h1 + (size_t)(band * 128) * 256;
#pragma unroll
        for (int q = 0; q < 8; q++) {
            int id = tid + q * 256;         // 2048 chunks of 16B per split
            int row = id >> 4, off = id & 15;
            cp16((char*)a0s + row * 272 + off * 16, s0 + row * 256 + off * 16);
            cp16((char*)a1s + row * 272 + off * 16, s1 + row * 256 + off * 16);
        }
        CP_COMMIT();
    }
    // dX (transposed) + bias tile
#pragma unroll
    for (int q = 0; q < 16; q++) {
        int e = tid + q * 256;              // 4096 = 128 rows x 32 i
        int row = e >> 5, i = e & 31;
        const float* cf = coeffs + ((long)(band * 128 + row) * NSEG + seg) * 128;
        dxT[i * 128 + row] = wb * cf[32 + i] + wc * cf[64 + i] + wd * cf[96 + i];
    }
    if (tid < 128) b2s[tid] = b2[ct * 128 + tid];

    CP_WAIT0();
    __syncthreads();

    // ---- mainloop: 8 ktiles, 2x8 warp subtiles, 4 split passes -----------
    float acc[2][8][4];
#pragma unroll
    for (int mt = 0; mt < 2; mt++)
#pragma unroll
        for (int nt = 0; nt < 8; nt++)
#pragma unroll
            for (int r = 0; r < 4; r++) acc[mt][nt][r] = 0.0f;

    const int arow = wm * 32 + g;           // + mt*16 (+8 inside frag)
#pragma unroll
    for (int kt = 0; kt < 8; kt++) {
        uint32_t afr[2][2][4];
#pragma unroll
        for (int mt = 0; mt < 2; mt++) {
            const char* ba0 = (const char*)a0s + (arow + mt * 16) * 272 + (kt * 16 + tq * 2) * 2;
            const char* ba1 = (const char*)a1s + (arow + mt * 16) * 272 + (kt * 16 + tq * 2) * 2;
            afr[0][mt][0] = *(const uint32_t*)(ba0);
            afr[0][mt][1] = *(const uint32_t*)(ba0 + 8 * 272);
            afr[0][mt][2] = *(const uint32_t*)(ba0 + 16);
            afr[0][mt][3] = *(const uint32_t*)(ba0 + 8 * 272 + 16);
            afr[1][mt][0] = *(const uint32_t*)(ba1);
            afr[1][mt][1] = *(const uint32_t*)(ba1 + 8 * 272);
            afr[1][mt][2] = *(const uint32_t*)(ba1 + 16);
            afr[1][mt][3] = *(const uint32_t*)(ba1 + 8 * 272 + 16);
        }
        uint2 bfr[2][8];
#pragma unroll
        for (int nt = 0; nt < 8; nt++) {
            uint32_t ntg = ct * 16 + wn * 8 + nt;
            uint32_t fo = ((ntg * 8 + kt) * 32 + lane);      // uint2 index
            bfr[0][nt] = ((const uint2*)g_wf0)[fo];
            bfr[1][nt] = ((const uint2*)g_wf1)[fo];
        }
#pragma unroll
        for (int mt = 0; mt < 2; mt++)
#pragma unroll
            for (int nt = 0; nt < 8; nt++) {
                mma16816(acc[mt][nt], afr[0][mt], (const uint32_t*)&bfr[0][nt]);
                mma16816(acc[mt][nt], afr[0][mt], (const uint32_t*)&bfr[1][nt]);
                mma16816(acc[mt][nt], afr[1][mt], (const uint32_t*)&bfr[0][nt]);
                mma16816(acc[mt][nt], afr[1][mt], (const uint32_t*)&bfr[1][nt]);
            }
    }

    // ---- epilogue: bias + tanh + dX contraction --------------------------
    // acc[mt][nt][r]: row = wm*32+mt*16+g+(r>=2)*8 ; col = wn*64+nt*8+tq*2+(r&1)
    float part[2][2][2];                    // [mt][p=rowhalf][hb=nt>=4]
#pragma unroll
    for (int mt = 0; mt < 2; mt++)
#pragma unroll
        for (int p = 0; p < 2; p++)
#pragma unroll
            for (int hb = 0; hb < 2; hb++) part[mt][p][hb] = 0.0f;

#pragma unroll
    for (int mt = 0; mt < 2; mt++)
#pragma unroll
        for (int nt = 0; nt < 8; nt++)
#pragma unroll
            for (int r = 0; r < 4; r++) {
                int col = wn * 64 + nt * 8 + tq * 2 + (r & 1);
                int row = wm * 32 + mt * 16 + g + ((r >> 1) << 3);
                int i   = col & 31;
                float t = fast_tanh(acc[mt][nt][r] + b2s[col]);
                part[mt][r >> 1][nt >> 2] += t * dxT[i * 128 + row];
            }
#pragma unroll
    for (int mt = 0; mt < 2; mt++)
#pragma unroll
        for (int p = 0; p < 2; p++)
#pragma unroll
            for (int hb = 0; hb < 2; hb++) {
                float v = part[mt][p][hb];
                v += __shfl_xor_sync(0xffffffffu, v, 1);
                v += __shfl_xor_sync(0xffffffffu, v, 2);
                part[mt][p][hb] = v;
            }
    if (tq == 0) {
#pragma unroll
        for (int mt = 0; mt < 2; mt++)
#pragma unroll
            for (int p = 0; p < 2; p++)
#pragma unroll
                for (int hb = 0; hb < 2; hb++) {
                    int row = wm * 32 + mt * 16 + g + p * 8;
                    int hl  = wn * 2 + hb;
                    kst[row * 4 + hl] = part[mt][p][hb];
                }
    }
    __syncthreads();

    // ---- RK4 bookkeeping: 128 rows x 4 h (consecutive) -> float4 ---------
    if (tid < 128) {
        int row = tid;
        float4 kv = *(float4*)&kst[row * 4];
        int gi = (band * 128 + row) * 128 + ct * 4;
        float* kout = (stage == 1) ? g_kbuf[1] : g_kbuf[0];
        if (stage == 0) {
            *(float4*)&kout[gi] = kv;
            *(float4*)&g_kacc[gi] = kv;
        } else if (stage == 3) {
            float4 ka = *(float4*)&g_kacc[gi];
            float4 zi = *(float4*)&g_zbuf[zflip][gi];
            float4 zo;
            zo.x = zi.x + (ka.x + kv.x) * (1.0f / 6.0f);
            zo.y = zi.y + (ka.y + kv.y) * (1.0f / 6.0f);
            zo.z = zi.z + (ka.z + kv.z) * (1.0f / 6.0f);
            zo.w = zi.w + (ka.w + kv.w) * (1.0f / 6.0f);
            *(float4*)&g_zbuf[zflip ^ 1][gi] = zo;
        } else {
            *(float4*)&kout[gi] = kv;
            float4 ka = *(float4*)&g_kacc[gi];
            ka.x += 2.0f * kv.x; ka.y += 2.0f * kv.y;
            ka.z += 2.0f * kv.z; ka.w += 2.0f * kv.w;
            *(float4*)&g_kacc[gi] = ka;
        }
    }
}

// ---------------- readout ---------------------------------------------------
__global__ void k_readout(const float* __restrict__ W_ro,
                          const float* __restrict__ b_ro) {
    int idx = blockIdx.x * blockDim.x + threadIdx.x;
    int b = idx >> 5, o = idx & 31;
    const float* zr = g_zbuf[1] + b * 128;   // NSEG odd -> final z in buf 1
    float acc = b_ro[o];
#pragma unroll
    for (int h = 0; h < 128; h++) acc += zr[h] * W_ro[h * 32 + o];
    g_y[idx] = acc;
}

// ---------------- evolve ----------------------------------------------------
__global__ void __launch_bounds__(256) k_evolve(const float* __restrict__ We1,
                                                const float* __restrict__ be1,
                                                const float* __restrict__ We2,
                                                const float* __restrict__ be2,
                                                float* __restrict__ out) {
    __shared__ float w1s[INN * HID];
    __shared__ float w2sE[HID * INN];
    __shared__ float ys[8][32];
    __shared__ float hsv[8][128];
    int tid = threadIdx.x;
    for (int i = tid; i < INN * HID; i += 256) w1s[i] = We1[i];
    for (int i = tid; i < HID * INN; i += 256) w2sE[i] = We2[i];
    __syncthreads();

    int r = tid >> 5, lane = tid & 31;
    int b = blockIdx.x * 8 + r;
    float y = g_y[b * 32 + lane];
    float be1r[4];
#pragma unroll
    for (int k = 0; k < 4; k++) be1r[k] = be1[k * 32 + lane];
    float be2r = be2[lane];
    const float hstep = 0.5f;

    auto ev = [&](float yin) -> float {
        ys[r][lane] = yin;
        __syncwarp();
        float h0 = be1r[0], h1 = be1r[1], h2 = be1r[2], h3 = be1r[3];
#pragma unroll
        for (int i = 0; i < 32; i++) {
            float yi = ys[r][i];
            h0 += yi * w1s[i * 128 + lane];
            h1 += yi * w1s[i * 128 + 32 + lane];
            h2 += yi * w1s[i * 128 + 64 + lane];
            h3 += yi * w1s[i * 128 + 96 + lane];
        }
        hsv[r][lane]      = fast_tanh(h0);
        hsv[r][lane + 32] = fast_tanh(h1);
        hsv[r][lane + 64] = fast_tanh(h2);
        hsv[r][lane + 96] = fast_tanh(h3);
        __syncwarp();
        float o = be2r;
#pragma unroll
        for (int j = 0; j < 128; j++) o += hsv[r][j] * w2sE[j * 32 + lane];
        __syncwarp();
        return o;
    };

    for (int s = 0; s < 10; s++) {
        float k1 = ev(y);
        float k2 = ev(y + 0.25f * k1);
        float k3 = ev(y + 0.25f * k2);
        float k4 = ev(y + 0.5f  * k3);
        y += (hstep / 6.0f) * (k1 + 2.0f * k2 + 2.0f * k3 + k4);
    }
    out[b * 32 + lane] = y;
}

// ---------------- host ------------------------------------------------------
extern "C" void kernel_launch(void* const* d_in, const int* in_sizes, int n_in,
                              void* d_out, int out_size) {
    const float* coeffs = (const float*)d_in[0];
    const float* W_init = (const float*)d_in[1];
    const float* b_init = (const float*)d_in[2];
    const float* W1     = (const float*)d_in[3];
    const float* b1     = (const float*)d_in[4];
    const float* W2     = (const float*)d_in[5];
    const float* b2     = (const float*)d_in[6];
    const float* W_ro   = (const float*)d_in[7];
    const float* b_ro   = (const float*)d_in[8];
    const float* We1    = (const float*)d_in[9];
    const float* be1    = (const float*)d_in[10];
    const float* We2    = (const float*)d_in[11];
    const float* be2    = (const float*)d_in[12];
    float* out = (float*)d_out;

    cudaFuncSetAttribute(k_gemm2, cudaFuncAttributeMaxDynamicSharedMemorySize, SMEMT);

    k_prep<<<2048, 256>>>(W2);
    k_init<<<(BN * HID) / 256, 256>>>(coeffs, W_init, b_init);

    dim3 gg(16, 32);
    for (int s = 0; s < NSEG; s++) {
        int zf = s & 1;
        k_hact<<<128, 256>>>(W1, b1, 0.0f, 0, zf);
        k_gemm2<<<gg, 256, SMEMT>>>(b2, coeffs, s, 1.0f, 0.0f, 0.0f, 0, zf);
        k_hact<<<128, 256>>>(W1, b1, 0.5f, 1, zf);
        k_gemm2<<<gg, 256, SMEMT>>>(b2, coeffs, s, 1.0f, 1.0f, 0.75f, 1, zf);
        k_hact<<<128, 256>>>(W1, b1, 0.5f, 2, zf);
        k_gemm2<<<gg, 256, SMEMT>>>(b2, coeffs, s, 1.0f, 1.0f, 0.75f, 2, zf);
        k_hact<<<128, 256>>>(W1, b1, 1.0f, 3, zf);
        int   seg4 = (s < NSEG - 1) ? s + 1 : NSEG - 1;
        float wc4  = (s < NSEG - 1) ? 0.0f : 2.0f;
        float wd4  = (s < NSEG - 1) ? 0.0f : 3.0f;
        k_gemm2<<<gg, 256, SMEMT>>>(b2, coeffs, seg4, 1.0f, wc4, wd4, 3, zf);
    }

    k_readout<<<(BN * OUTN) / 256, 256>>>(W_ro, b_ro);
    k_evolve<<<BN / 8, 256>>>(We1, be1, We2, be2, out);
}

// round 11
// speedup vs baseline: 3.5176x; 1.0367x over previous
#include <cuda_runtime.h>
#include <cuda_bf16.h>
#include <stdint.h>

#define BN   2048
#define HID  128
#define INN  32
#define OUTN 32
#define NSEG 63

// ---------------- device scratch -------------------------------------------
__device__ float g_zbuf[2][BN * HID];
__device__ float g_kbuf[2][BN * HID];
__device__ float g_kacc[BN * HID];
__device__ float g_dx[BN * INN];             // per-stage dX(t), row-major
__device__ float g_y[BN * OUTN];
__device__ __nv_bfloat16 g_h0[BN * HID];     // hact split 0, row-major [row][k]
__device__ __nv_bfloat16 g_h1[BN * HID];     // hact split 1
__device__ __nv_bfloat16 g_wf0[4096 * 128];  // W2 split 0, B-fragment order
__device__ __nv_bfloat16 g_wf1[4096 * 128];  // W2 split 1

// ---------------- helpers ---------------------------------------------------
__device__ __forceinline__ float fast_tanh(float x) {
    float ax = fabsf(x);
    float e  = __expf(-2.0f * ax);
    float r  = __fdividef(1.0f - e, 1.0f + e);
    return copysignf(r, x);
}
__device__ __forceinline__ void cp16(void* sdst, const void* gsrc) {
    unsigned s = (unsigned)__cvta_generic_to_shared(sdst);
    asm volatile("cp.async.cg.shared.global [%0], [%1], 16;" :: "r"(s), "l"(gsrc));
}
#define CP_COMMIT() asm volatile("cp.async.commit_group;" ::: "memory")
#define CP_WAIT0()  asm volatile("cp.async.wait_group 0;"  ::: "memory")
#define CP_WAIT1()  asm volatile("cp.async.wait_group 1;"  ::: "memory")

__device__ __forceinline__ void mma16816(float* d, const uint32_t* a, const uint32_t* b) {
    asm volatile(
        "mma.sync.aligned.m16n8k16.row.col.f32.bf16.bf16.f32 "
        "{%0,%1,%2,%3}, {%4,%5,%6,%7}, {%8,%9}, {%0,%1,%2,%3};"
        : "+f"(d[0]), "+f"(d[1]), "+f"(d[2]), "+f"(d[3])
        : "r"(a[0]), "r"(a[1]), "r"(a[2]), "r"(a[3]), "r"(b[0]), "r"(b[1]));
}

// ---------------- one-time: W2 bf16 splits in B-fragment order --------------
// Layout: [ntile(512)][ktile(8)][lane(32)][4 bf16]
__global__ void k_prep(const float* __restrict__ W2) {
    int idx = blockIdx.x * 256 + threadIdx.x;   // 524288 = 128k * 4096n
    int k = idx >> 12;
    int n = idx & 4095;
    float w = W2[(long)k * 4096 + n];
    __nv_bfloat16 w0 = __float2bfloat16(w);
    __nv_bfloat16 w1 = __float2bfloat16(w - __bfloat162float(w0));
    int nt = n >> 3, kt = k >> 4;
    int t  = ((n & 7) << 2) | ((k >> 1) & 3);
    int r  = (k >> 3) & 1, hh = k & 1;
    uint32_t pos = ((uint32_t)((nt * 8 + kt) * 32 + t) << 2) + (r << 1) + hh;
    g_wf0[pos] = w0;
    g_wf1[pos] = w1;
}

// ---------------- init: z0 = a[:,0] @ W_init + b_init ----------------------
__global__ void k_init(const float* __restrict__ coeffs,
                       const float* __restrict__ W_init,
                       const float* __restrict__ b_init) {
    int idx = blockIdx.x * blockDim.x + threadIdx.x;
    int b = idx >> 7, c = idx & 127;
    const float* a0 = coeffs + (long)b * NSEG * 128;
    float acc = b_init[c];
#pragma unroll
    for (int i = 0; i < INN; i++) acc += a0[i] * W_init[i * HID + c];
    g_zbuf[0][idx] = acc;
}

// ---------------- per-stage: hact splits + dX ------------------------------
__global__ void __launch_bounds__(256) k_hact(const float* __restrict__ W1,
                                              const float* __restrict__ b1,
                                              const float* __restrict__ coeffs,
                                              int seg, float wb, float wc, float wd,
                                              float alpha, int stage, int zflip) {
    __shared__ float zs[16 * 128];
    const int tid = threadIdx.x;
    const int b0  = blockIdx.x * 16;
    const float* zin = g_zbuf[zflip];
    const float* kin = (stage == 2) ? g_kbuf[1] : g_kbuf[0];

#pragma unroll
    for (int q = 0; q < 2; q++) {
        int i4 = tid + 256 * q;              // 512 float4
        int r = i4 >> 5, m4 = i4 & 31;
        float4 v = *(const float4*)&zin[(b0 + r) * 128 + m4 * 4];
        if (stage != 0) {
            float4 kv = *(const float4*)&kin[(b0 + r) * 128 + m4 * 4];
            v.x += alpha * kv.x; v.y += alpha * kv.y;
            v.z += alpha * kv.z; v.w += alpha * kv.w;
        }
        *(float4*)&zs[r * 128 + m4 * 4] = v;
    }
    // dX for this stage -> g_dx
#pragma unroll
    for (int q = 0; q < 2; q++) {
        int e = tid + q * 256;               // 512 = 16 rows x 32 i
        int r = e >> 5, i = e & 31;
        const float* cf = coeffs + ((long)(b0 + r) * NSEG + seg) * 128;
        g_dx[(b0 + r) * 32 + i] = wb * cf[32 + i] + wc * cf[64 + i] + wd * cf[96 + i];
    }
    __syncthreads();

    int c = tid & 127, half = tid >> 7;      // rows half*8 .. half*8+7
    float a8[8];
#pragma unroll
    for (int r = 0; r < 8; r++) a8[r] = 0.0f;
    for (int k4 = 0; k4 < 128; k4 += 4) {
        float w0  = W1[(k4 + 0) * 128 + c];
        float w1v = W1[(k4 + 1) * 128 + c];
        float w2v = W1[(k4 + 2) * 128 + c];
        float w3v = W1[(k4 + 3) * 128 + c];
#pragma unroll
        for (int r = 0; r < 8; r++) {
            float4 zv = *(const float4*)&zs[(half * 8 + r) * 128 + k4];
            a8[r] = fmaf(zv.x, w0, fmaf(zv.y, w1v, fmaf(zv.z, w2v, fmaf(zv.w, w3v, a8[r]))));
        }
    }
    float bb1 = b1[c];
#pragma unroll
    for (int r = 0; r < 8; r++) {
        int rowg = b0 + half * 8 + r;
        float h = fmaxf(a8[r] + bb1, 0.0f);
        __nv_bfloat16 h0 = __float2bfloat16(h);
        __nv_bfloat16 h1 = __float2bfloat16(h - __bfloat162float(h0));
        g_h0[rowg * 128 + c] = h0;
        g_h1[rowg * 128 + c] = h1;
    }
}

// ---------------- per-stage: HMMA GEMM2 + tanh + contraction + RK4 ---------
// CTA: 128 rows x 64 cols. 8 warps = 4(m) x 2(n). Warp tile: 32m x 32n.
// Grid (16, 64): x = 128-row band, y = 64-col tile. 3 split passes.
#define SA0   0                              // 128*272 = 34816
#define SA1   34816
#define SBB   69632                          // B staging [2][4096]
#define SDX   77824                          // dxT[32][128] f32 = 16384
#define SKST  94208                          // kst[128][2] f32 = 1024
#define SB2   95232                          // b2s[64] = 256
#define SMEMT 95488

__global__ void __launch_bounds__(256, 2) k_gemm2(
    const float* __restrict__ b2, int stage, int zflip)
{
    extern __shared__ __align__(16) char sm[];
    __nv_bfloat16* a0s = (__nv_bfloat16*)(sm + SA0);
    __nv_bfloat16* a1s = (__nv_bfloat16*)(sm + SA1);
    char* sB   = sm + SBB;
    float* dxT = (float*)(sm + SDX);        // [i][row]
    float* kst = (float*)(sm + SKST);       // [row][2]
    float* b2s = (float*)(sm + SB2);

    const int tid  = threadIdx.x;
    const int band = blockIdx.x;            // 0..15
    const int ct   = blockIdx.y;            // 0..63
    const int lane = tid & 31, wid = tid >> 5;
    const int wm = wid & 3, wn = wid >> 2;  // 4(m) x 2(n)
    const int g = lane >> 2, tq = lane & 3;

    // ---- group 0: stage A splits into padded smem ----
    {
        const char* s0 = (const char*)g_h0 + (size_t)(band * 128) * 256;
        const char* s1 = (const char*)g_h1 + (size_t)(band * 128) * 256;
#pragma unroll
        for (int q = 0; q < 8; q++) {
            int id = tid + q * 256;         // 2048 16B chunks per split
            int row = id >> 4, off = id & 15;
            cp16((char*)a0s + row * 272 + off * 16, s0 + row * 256 + off * 16);
            cp16((char*)a1s + row * 272 + off * 16, s1 + row * 256 + off * 16);
        }
        CP_COMMIT();
    }
    // dxT (transpose of g_dx band) + bias tile
#pragma unroll
    for (int q = 0; q < 16; q++) {
        int e = tid + q * 256;              // 4096 = 128 rows x 32 i
        int row = e >> 5, i = e & 31;
        dxT[i * 128 + row] = g_dx[(band * 128 + row) * 32 + i];
    }
    if (tid < 64) b2s[tid] = b2[ct * 64 + tid];

    // ---- group 1: B fragments for kt=0 ----
    {
        int c = tid >> 4, j = c >> 1, s = c & 1, o = tid & 15;
        const char* src = (const char*)(s ? g_wf1 : g_wf0)
                        + ((size_t)((ct * 8 + j) * 8 + 0)) * 256 + o * 16;
        cp16(sB + ((j * 2 + s) * 256) + o * 16, src);
        CP_COMMIT();
    }

    float acc[2][4][4];
#pragma unroll
    for (int mt = 0; mt < 2; mt++)
#pragma unroll
        for (int nt = 0; nt < 4; nt++)
#pragma unroll
            for (int r = 0; r < 4; r++) acc[mt][nt][r] = 0.0f;

    const int arow = wm * 32 + g;
#pragma unroll
    for (int kt = 0; kt < 8; kt++) {
        const int cur = kt & 1;
        if (kt < 7) {   // prefetch kt+1 into other buffer
            int c = tid >> 4, j = c >> 1, s = c & 1, o = tid & 15;
            const char* src = (const char*)(s ? g_wf1 : g_wf0)
                            + ((size_t)((ct * 8 + j) * 8 + kt + 1)) * 256 + o * 16;
            cp16(sB + (cur ^ 1) * 4096 + ((j * 2 + s) * 256) + o * 16, src);
            CP_COMMIT();
            CP_WAIT1();
        } else {
            CP_WAIT0();
        }
        __syncthreads();

        uint32_t afr[2][2][4];
#pragma unroll
        for (int mt = 0; mt < 2; mt++) {
            const char* ba0 = (const char*)a0s + (arow + mt * 16) * 272 + (kt * 16 + tq * 2) * 2;
            const char* ba1 = (const char*)a1s + (arow + mt * 16) * 272 + (kt * 16 + tq * 2) * 2;
            afr[0][mt][0] = *(const uint32_t*)(ba0);
            afr[0][mt][1] = *(const uint32_t*)(ba0 + 8 * 272);
            afr[0][mt][2] = *(const uint32_t*)(ba0 + 16);
            afr[0][mt][3] = *(const uint32_t*)(ba0 + 8 * 272 + 16);
            afr[1][mt][0] = *(const uint32_t*)(ba1);
            afr[1][mt][1] = *(const uint32_t*)(ba1 + 8 * 272);
            afr[1][mt][2] = *(const uint32_t*)(ba1 + 16);
            afr[1][mt][3] = *(const uint32_t*)(ba1 + 8 * 272 + 16);
        }
#pragma unroll
        for (int nt = 0; nt < 4; nt++) {
            const char* base = sB + cur * 4096 + ((wn * 4 + nt) * 2) * 256 + lane * 8;
            uint2 b0f = *(const uint2*)(base);
            uint2 b1f = *(const uint2*)(base + 256);
#pragma unroll
            for (int mt = 0; mt < 2; mt++) {
                mma16816(acc[mt][nt], afr[0][mt], (const uint32_t*)&b0f);  // h0*w0
                mma16816(acc[mt][nt], afr[0][mt], (const uint32_t*)&b1f);  // h0*w1
                mma16816(acc[mt][nt], afr[1][mt], (const uint32_t*)&b0f);  // h1*w0
            }
        }
        __syncthreads();   // protect cur buffer before next prefetch overwrite
    }

    // ---- epilogue: bias + tanh + dX contraction --------------------------
    // acc[mt][nt][r]: row = wm*32+mt*16+g+(r>>1)*8 ; col = wn*32+nt*8+tq*2+(r&1)
    float part[2][2] = {{0.f, 0.f}, {0.f, 0.f}};
#pragma unroll
    for (int mt = 0; mt < 2; mt++)
#pragma unroll
        for (int nt = 0; nt < 4; nt++)
#pragma unroll
            for (int r = 0; r < 4; r++) {
                int i   = nt * 8 + tq * 2 + (r & 1);
                int col = wn * 32 + i;
                int row = wm * 32 + mt * 16 + g + ((r >> 1) << 3);
                float t = fast_tanh(acc[mt][nt][r] + b2s[col]);
                part[mt][r >> 1] += t * dxT[i * 128 + row];
            }
#pragma unroll
    for (int mt = 0; mt < 2; mt++)
#pragma unroll
        for (int p = 0; p < 2; p++) {
            float v = part[mt][p];
            v += __shfl_xor_sync(0xffffffffu, v, 1);
            v += __shfl_xor_sync(0xffffffffu, v, 2);
            part[mt][p] = v;
        }
    if (tq == 0) {
#pragma unroll
        for (int mt = 0; mt < 2; mt++)
#pragma unroll
            for (int p = 0; p < 2; p++) {
                int row = wm * 32 + mt * 16 + g + p * 8;
                kst[row * 2 + wn] = part[mt][p];
            }
    }
    __syncthreads();

    // ---- RK4 bookkeeping: 128 rows x 2 h -> float2 -----------------------
    if (tid < 128) {
        int row = tid;
        float2 kv = *(float2*)&kst[row * 2];
        int gi = (band * 128 + row) * 128 + ct * 2;
        float* kout = (stage == 1) ? g_kbuf[1] : g_kbuf[0];
        if (stage == 0) {
            *(float2*)&kout[gi] = kv;
            *(float2*)&g_kacc[gi] = kv;
        } else if (stage == 3) {
            float2 ka = *(float2*)&g_kacc[gi];
            float2 zi = *(float2*)&g_zbuf[zflip][gi];
            float2 zo;
            zo.x = zi.x + (ka.x + kv.x) * (1.0f / 6.0f);
            zo.y = zi.y + (ka.y + kv.y) * (1.0f / 6.0f);
            *(float2*)&g_zbuf[zflip ^ 1][gi] = zo;
        } else {
            *(float2*)&kout[gi] = kv;
            float2 ka = *(float2*)&g_kacc[gi];
            ka.x += 2.0f * kv.x; ka.y += 2.0f * kv.y;
            *(float2*)&g_kacc[gi] = ka;
        }
    }
}

// ---------------- readout ---------------------------------------------------
__global__ void k_readout(const float* __restrict__ W_ro,
                          const float* __restrict__ b_ro) {
    int idx = blockIdx.x * blockDim.x + threadIdx.x;
    int b = idx >> 5, o = idx & 31;
    const float* zr = g_zbuf[1] + b * 128;   // NSEG odd -> final z in buf 1
    float acc = b_ro[o];
#pragma unroll
    for (int h = 0; h < 128; h++) acc += zr[h] * W_ro[h * 32 + o];
    g_y[idx] = acc;
}

// ---------------- evolve ----------------------------------------------------
__global__ void __launch_bounds__(256) k_evolve(const float* __restrict__ We1,
                                                const float* __restrict__ be1,
                                                const float* __restrict__ We2,
                                                const float* __restrict__ be2,
                                                float* __restrict__ out) {
    __shared__ float w1s[INN * HID];
    __shared__ float w2sE[HID * INN];
    __shared__ float ys[8][32];
    __shared__ float hsv[8][128];
    int tid = threadIdx.x;
    for (int i = tid; i < INN * HID; i += 256) w1s[i] = We1[i];
    for (int i = tid; i < HID * INN; i += 256) w2sE[i] = We2[i];
    __syncthreads();

    int r = tid >> 5, lane = tid & 31;
    int b = blockIdx.x * 8 + r;
    float y = g_y[b * 32 + lane];
    float be1r[4];
#pragma unroll
    for (int k = 0; k < 4; k++) be1r[k] = be1[k * 32 + lane];
    float be2r = be2[lane];
    const float hstep = 0.5f;

    auto ev = [&](float yin) -> float {
        ys[r][lane] = yin;
        __syncwarp();
        float h0 = be1r[0], h1 = be1r[1], h2 = be1r[2], h3 = be1r[3];
#pragma unroll
        for (int i = 0; i < 32; i++) {
            float yi = ys[r][i];
            h0 += yi * w1s[i * 128 + lane];
            h1 += yi * w1s[i * 128 + 32 + lane];
            h2 += yi * w1s[i * 128 + 64 + lane];
            h3 += yi * w1s[i * 128 + 96 + lane];
        }
        hsv[r][lane]      = fast_tanh(h0);
        hsv[r][lane + 32] = fast_tanh(h1);
        hsv[r][lane + 64] = fast_tanh(h2);
        hsv[r][lane + 96] = fast_tanh(h3);
        __syncwarp();
        float o = be2r;
#pragma unroll
        for (int j = 0; j < 128; j++) o += hsv[r][j] * w2sE[j * 32 + lane];
        __syncwarp();
        return o;
    };

    for (int s = 0; s < 10; s++) {
        float k1 = ev(y);
        float k2 = ev(y + 0.25f * k1);
        float k3 = ev(y + 0.25f * k2);
        float k4 = ev(y + 0.5f  * k3);
        y += (hstep / 6.0f) * (k1 + 2.0f * k2 + 2.0f * k3 + k4);
    }
    out[b * 32 + lane] = y;
}

// ---------------- host ------------------------------------------------------
extern "C" void kernel_launch(void* const* d_in, const int* in_sizes, int n_in,
                              void* d_out, int out_size) {
    const float* coeffs = (const float*)d_in[0];
    const float* W_init = (const float*)d_in[1];
    const float* b_init = (const float*)d_in[2];
    const float* W1     = (const float*)d_in[3];
    const float* b1     = (const float*)d_in[4];
    const float* W2     = (const float*)d_in[5];
    const float* b2     = (const float*)d_in[6];
    const float* W_ro   = (const float*)d_in[7];
    const float* b_ro   = (const float*)d_in[8];
    const float* We1    = (const float*)d_in[9];
    const float* be1    = (const float*)d_in[10];
    const float* We2    = (const float*)d_in[11];
    const float* be2    = (const float*)d_in[12];
    float* out = (float*)d_out;

    cudaFuncSetAttribute(k_gemm2, cudaFuncAttributeMaxDynamicSharedMemorySize, SMEMT);

    k_prep<<<2048, 256>>>(W2);
    k_init<<<(BN * HID) / 256, 256>>>(coeffs, W_init, b_init);

    dim3 gg(16, 64);
    for (int s = 0; s < NSEG; s++) {
        int zf = s & 1;
        k_hact<<<128, 256>>>(W1, b1, coeffs, s, 1.0f, 0.0f, 0.0f, 0.0f, 0, zf);
        k_gemm2<<<gg, 256, SMEMT>>>(b2, 0, zf);
        k_hact<<<128, 256>>>(W1, b1, coeffs, s, 1.0f, 1.0f, 0.75f, 0.5f, 1, zf);
        k_gemm2<<<gg, 256, SMEMT>>>(b2, 1, zf);
        k_hact<<<128, 256>>>(W1, b1, coeffs, s, 1.0f, 1.0f, 0.75f, 0.5f, 2, zf);
        k_gemm2<<<gg, 256, SMEMT>>>(b2, 2, zf);
        int   seg4 = (s < NSEG - 1) ? s + 1 : NSEG - 1;
        float wc4  = (s < NSEG - 1) ? 0.0f : 2.0f;
        float wd4  = (s < NSEG - 1) ? 0.0f : 3.0f;
        k_hact<<<128, 256>>>(W1, b1, coeffs, seg4, 1.0f, wc4, wd4, 1.0f, 3, zf);
        k_gemm2<<<gg, 256, SMEMT>>>(b2, 3, zf);
    }

    k_readout<<<(BN * OUTN) / 256, 256>>>(W_ro, b_ro);
    k_evolve<<<BN / 8, 256>>>(We1, be1, We2, be2, out);
}

// round 14
// speedup vs baseline: 4.7781x; 1.3583x over previous
#include <cuda_runtime.h>
#include <cuda_bf16.h>
#include <stdint.h>

#define BN   2048
#define HID  128
#define INN  32
#define OUTN 32
#define NSEG 63

// ---------------- device scratch -------------------------------------------
__device__ float g_zbuf[2][BN * HID];
__device__ float g_kbuf[2][BN * HID];
__device__ float g_kacc[BN * HID];
__device__ float g_dx[BN * INN];             // per-stage dX(t), row-major
__device__ float g_y[BN * OUTN];
__device__ __nv_bfloat16 g_h0[BN * HID];     // hact split 0, row-major [row][k]
__device__ __nv_bfloat16 g_h1[BN * HID];     // hact split 1
__device__ __nv_bfloat16 g_wf0[4096 * 128];  // W2 split 0, B-fragment order
__device__ __nv_bfloat16 g_wf1[4096 * 128];  // W2 split 1

// ---------------- helpers ---------------------------------------------------
__device__ __forceinline__ float fast_tanh(float x) {
    float ax = fabsf(x);
    float e  = __expf(-2.0f * ax);
    float r  = __fdividef(1.0f - e, 1.0f + e);
    return copysignf(r, x);
}
__device__ __forceinline__ void cp16(void* sdst, const void* gsrc) {
    unsigned s = (unsigned)__cvta_generic_to_shared(sdst);
    asm volatile("cp.async.cg.shared.global [%0], [%1], 16;" :: "r"(s), "l"(gsrc));
}
#define CP_COMMIT() asm volatile("cp.async.commit_group;" ::: "memory")
#define CP_WAIT0()  asm volatile("cp.async.wait_group 0;"  ::: "memory")

__device__ __forceinline__ void mma16816(float* d, const uint32_t* a, const uint32_t* b) {
    asm volatile(
        "mma.sync.aligned.m16n8k16.row.col.f32.bf16.bf16.f32 "
        "{%0,%1,%2,%3}, {%4,%5,%6,%7}, {%8,%9}, {%0,%1,%2,%3};"
        : "+f"(d[0]), "+f"(d[1]), "+f"(d[2]), "+f"(d[3])
        : "r"(a[0]), "r"(a[1]), "r"(a[2]), "r"(a[3]), "r"(b[0]), "r"(b[1]));
}
__device__ __forceinline__ void ldmatrix_x4(uint32_t* r, uint32_t saddr) {
    asm volatile("ldmatrix.sync.aligned.m8n8.x4.shared.b16 {%0,%1,%2,%3}, [%4];"
        : "=r"(r[0]), "=r"(r[1]), "=r"(r[2]), "=r"(r[3]) : "r"(saddr));
}

// ---------------- one-time: W2 bf16 splits in B-fragment order --------------
// Layout: [ntile(512)][ktile(8)][lane(32)][4 bf16]
__global__ void k_prep(const float* __restrict__ W2) {
    int idx = blockIdx.x * 256 + threadIdx.x;   // 524288 = 128k * 4096n
    int k = idx >> 12;
    int n = idx & 4095;
    float w = W2[(long)k * 4096 + n];
    __nv_bfloat16 w0 = __float2bfloat16(w);
    __nv_bfloat16 w1 = __float2bfloat16(w - __bfloat162float(w0));
    int nt = n >> 3, kt = k >> 4;
    int t  = ((n & 7) << 2) | ((k >> 1) & 3);
    int r  = (k >> 3) & 1, hh = k & 1;
    uint32_t pos = ((uint32_t)((nt * 8 + kt) * 32 + t) << 2) + (r << 1) + hh;
    g_wf0[pos] = w0;
    g_wf1[pos] = w1;
}

// ---------------- init: z0 = a[:,0] @ W_init + b_init ----------------------
__global__ void k_init(const float* __restrict__ coeffs,
                       const float* __restrict__ W_init,
                       const float* __restrict__ b_init) {
    int idx = blockIdx.x * blockDim.x + threadIdx.x;
    int b = idx >> 7, c = idx & 127;
    const float* a0 = coeffs + (long)b * NSEG * 128;
    float acc = b_init[c];
#pragma unroll
    for (int i = 0; i < INN; i++) acc += a0[i] * W_init[i * HID + c];
    g_zbuf[0][idx] = acc;
}

// ---------------- per-stage: hact splits + dX ------------------------------
__global__ void __launch_bounds__(256) k_hact(const float* __restrict__ W1,
                                              const float* __restrict__ b1,
                                              const float* __restrict__ coeffs,
                                              int seg, float wb, float wc, float wd,
                                              float alpha, int stage, int zflip) {
    __shared__ float zs[16 * 128];
    const int tid = threadIdx.x;
    const int b0  = blockIdx.x * 16;
    const float* zin = g_zbuf[zflip];
    const float* kin = (stage == 2) ? g_kbuf[1] : g_kbuf[0];

#pragma unroll
    for (int q = 0; q < 2; q++) {
        int i4 = tid + 256 * q;              // 512 float4
        int r = i4 >> 5, m4 = i4 & 31;
        float4 v = *(const float4*)&zin[(b0 + r) * 128 + m4 * 4];
        if (stage != 0) {
            float4 kv = *(const float4*)&kin[(b0 + r) * 128 + m4 * 4];
            v.x += alpha * kv.x; v.y += alpha * kv.y;
            v.z += alpha * kv.z; v.w += alpha * kv.w;
        }
        *(float4*)&zs[r * 128 + m4 * 4] = v;
    }
    // dX for this stage -> g_dx
#pragma unroll
    for (int q = 0; q < 2; q++) {
        int e = tid + q * 256;               // 512 = 16 rows x 32 i
        int r = e >> 5, i = e & 31;
        const float* cf = coeffs + ((long)(b0 + r) * NSEG + seg) * 128;
        g_dx[(b0 + r) * 32 + i] = wb * cf[32 + i] + wc * cf[64 + i] + wd * cf[96 + i];
    }
    __syncthreads();

    int c = tid & 127, half = tid >> 7;      // rows half*8 .. half*8+7
    float a8[8];
#pragma unroll
    for (int r = 0; r < 8; r++) a8[r] = 0.0f;
    for (int k4 = 0; k4 < 128; k4 += 4) {
        float w0  = W1[(k4 + 0) * 128 + c];
        float w1v = W1[(k4 + 1) * 128 + c];
        float w2v = W1[(k4 + 2) * 128 + c];
        float w3v = W1[(k4 + 3) * 128 + c];
#pragma unroll
        for (int r = 0; r < 8; r++) {
            float4 zv = *(const float4*)&zs[(half * 8 + r) * 128 + k4];
            a8[r] = fmaf(zv.x, w0, fmaf(zv.y, w1v, fmaf(zv.z, w2v, fmaf(zv.w, w3v, a8[r]))));
        }
    }
    float bb1 = b1[c];
#pragma unroll
    for (int r = 0; r < 8; r++) {
        int rowg = b0 + half * 8 + r;
        float h = fmaxf(a8[r] + bb1, 0.0f);
        __nv_bfloat16 h0 = __float2bfloat16(h);
        __nv_bfloat16 h1 = __float2bfloat16(h - __bfloat162float(h0));
        g_h0[rowg * 128 + c] = h0;
        g_h1[rowg * 128 + c] = h1;
    }
}

// ---------------- per-stage: HMMA GEMM2 + tanh + contraction + RK4 ---------
// CTA: 128 rows x 64 cols. 8 warps = 4(m) x 2(n). Warp tile: 32m x 32n.
// Grid (16, 64). All A+B staged upfront; barrier-free mainloop; 3 split passes.
#define SA0   0                              // 128*272 = 34816
#define SA1   34816                          // -> 69632
#define SBB   69632                          // B all ktiles: 8*4096 = 32768 -> 102400
                                             // (reused post-mainloop as dxT[32][132])
#define SKST  102400                         // kst[128][2] f32 = 1024
#define SB2   103424                         // b2s[64] = 256
#define SMEMT 103680

__global__ void __launch_bounds__(256, 2) k_gemm2(
    const float* __restrict__ b2, int stage, int zflip)
{
    extern __shared__ __align__(16) char sm[];
    char* sB   = sm + SBB;
    float* kst = (float*)(sm + SKST);       // [row][2]
    float* b2s = (float*)(sm + SB2);
    const uint32_t smb = (uint32_t)__cvta_generic_to_shared(sm);

    const int tid  = threadIdx.x;
    const int band = blockIdx.x;            // 0..15
    const int ct   = blockIdx.y;            // 0..63
    const int lane = tid & 31, wid = tid >> 5;
    const int wm = wid & 3, wn = wid >> 2;  // 4(m) x 2(n)
    const int g = lane >> 2, tq = lane & 3;

    // ---- stage A splits (padded 272B stride) + ALL B ktiles upfront ----
    {
        const char* s0 = (const char*)g_h0 + (size_t)(band * 128) * 256;
        const char* s1 = (const char*)g_h1 + (size_t)(band * 128) * 256;
#pragma unroll
        for (int q = 0; q < 8; q++) {
            int id = tid + q * 256;         // 2048 16B chunks per split
            int row = id >> 4, off = id & 15;
            cp16(sm + SA0 + row * 272 + off * 16, s0 + row * 256 + off * 16);
            cp16(sm + SA1 + row * 272 + off * 16, s1 + row * 256 + off * 16);
        }
#pragma unroll
        for (int q = 0; q < 8; q++) {
            int id = tid + q * 256;         // 2048 16B chunks of B
            int kt = id >> 8, rr = id & 255;
            int js = rr >> 4, o = rr & 15;  // js = ntile*2 + split
            const char* src = (const char*)((js & 1) ? g_wf1 : g_wf0)
                            + ((size_t)((ct * 8 + (js >> 1)) * 8 + kt)) * 256 + o * 16;
            cp16(sB + kt * 4096 + js * 256 + o * 16, src);
        }
        CP_COMMIT();
    }
    if (tid < 64) b2s[tid] = b2[ct * 64 + tid];

    CP_WAIT0();
    __syncthreads();

    // ---- barrier-free mainloop: 8 ktiles, ldmatrix A, 3 split passes -----
    float acc[2][4][4];
#pragma unroll
    for (int mt = 0; mt < 2; mt++)
#pragma unroll
        for (int nt = 0; nt < 4; nt++)
#pragma unroll
            for (int r = 0; r < 4; r++) acc[mt][nt][r] = 0.0f;

    const int lrow = lane & 15, lcol = lane >> 4;
#pragma unroll
    for (int kt = 0; kt < 8; kt++) {
        uint32_t afr0[2][4], afr1[2][4];
#pragma unroll
        for (int mt = 0; mt < 2; mt++) {
            uint32_t ad = smb + SA0 + (uint32_t)(wm * 32 + mt * 16 + lrow) * 272
                        + kt * 32 + lcol * 16;
            ldmatrix_x4(afr0[mt], ad);
            ldmatrix_x4(afr1[mt], ad + 34816);
        }
#pragma unroll
        for (int nt = 0; nt < 4; nt++) {
            const char* base = sB + kt * 4096 + ((wn * 4 + nt) * 2) * 256 + lane * 8;
            uint2 b0f = *(const uint2*)(base);
            uint2 b1f = *(const uint2*)(base + 256);
#pragma unroll
            for (int mt = 0; mt < 2; mt++) {
                mma16816(acc[mt][nt], afr0[mt], (const uint32_t*)&b0f);  // h0*w0
                mma16816(acc[mt][nt], afr0[mt], (const uint32_t*)&b1f);  // h0*w1
                mma16816(acc[mt][nt], afr1[mt], (const uint32_t*)&b0f);  // h1*w0
            }
        }
    }

    // ---- dX transpose into the dead B staging area (pad 132) -------------
    __syncthreads();                         // everyone done reading sB
    float* dxT = (float*)sB;                 // [i][row] stride 132
    {
        const float* dxg = g_dx + (size_t)(band * 128) * 32;
#pragma unroll
        for (int q = 0; q < 16; q++) {
            int e = tid + q * 256;           // 4096 = 128 rows x 32 i
            int row = e >> 5, i = e & 31;
            dxT[i * 132 + row] = dxg[row * 32 + i];
        }
    }
    __syncthreads();

    // ---- epilogue: bias + tanh + dX contraction --------------------------
    // acc[mt][nt][r]: row = wm*32+mt*16+g+(r>>1)*8 ; col = wn*32+nt*8+tq*2+(r&1)
    float part[2][2] = {{0.f, 0.f}, {0.f, 0.f}};
#pragma unroll
    for (int mt = 0; mt < 2; mt++)
#pragma unroll
        for (int nt = 0; nt < 4; nt++)
#pragma unroll
            for (int r = 0; r < 4; r++) {
                int i   = nt * 8 + tq * 2 + (r & 1);
                int col = wn * 32 + i;
                int row = wm * 32 + mt * 16 + g + ((r >> 1) << 3);
                float t = fast_tanh(acc[mt][nt][r] + b2s[col]);
                part[mt][r >> 1] += t * dxT[i * 132 + row];
            }
#pragma unroll
    for (int mt = 0; mt < 2; mt++)
#pragma unroll
        for (int p = 0; p < 2; p++) {
            float v = part[mt][p];
            v += __shfl_xor_sync(0xffffffffu, v, 1);
            v += __shfl_xor_sync(0xffffffffu, v, 2);
            part[mt][p] = v;
        }
    if (tq == 0) {
#pragma unroll
        for (int mt = 0; mt < 2; mt++)
#pragma unroll
            for (int p = 0; p < 2; p++) {
                int row = wm * 32 + mt * 16 + g + p * 8;
                kst[row * 2 + wn] = part[mt][p];
            }
    }
    __syncthreads();

    // ---- RK4 bookkeeping: 128 rows x 2 h -> float2 -----------------------
    if (tid < 128) {
        int row = tid;
        float2 kv = *(float2*)&kst[row * 2];
        int gi = (band * 128 + row) * 128 + ct * 2;
        float* kout = (stage == 1) ? g_kbuf[1] : g_kbuf[0];
        if (stage == 0) {
            *(float2*)&kout[gi] = kv;
            *(float2*)&g_kacc[gi] = kv;
        } else if (stage == 3) {
            float2 ka = *(float2*)&g_kacc[gi];
            float2 zi = *(float2*)&g_zbuf[zflip][gi];
            float2 zo;
            zo.x = zi.x + (ka.x + kv.x) * (1.0f / 6.0f);
            zo.y = zi.y + (ka.y + kv.y) * (1.0f / 6.0f);
            *(float2*)&g_zbuf[zflip ^ 1][gi] = zo;
        } else {
            *(float2*)&kout[gi] = kv;
            float2 ka = *(float2*)&g_kacc[gi];
            ka.x += 2.0f * kv.x; ka.y += 2.0f * kv.y;
            *(float2*)&g_kacc[gi] = ka;
        }
    }
}

// ---------------- readout ---------------------------------------------------
__global__ void k_readout(const float* __restrict__ W_ro,
                          const float* __restrict__ b_ro) {
    int idx = blockIdx.x * blockDim.x + threadIdx.x;
    int b = idx >> 5, o = idx & 31;
    const float* zr = g_zbuf[1] + b * 128;   // NSEG odd -> final z in buf 1
    float acc = b_ro[o];
#pragma unroll
    for (int h = 0; h < 128; h++) acc += zr[h] * W_ro[h * 32 + o];
    g_y[idx] = acc;
}

// ---------------- evolve ----------------------------------------------------
__global__ void __launch_bounds__(256) k_evolve(const float* __restrict__ We1,
                                                const float* __restrict__ be1,
                                                const float* __restrict__ We2,
                                                const float* __restrict__ be2,
                                                float* __restrict__ out) {
    __shared__ float w1s[INN * HID];
    __shared__ float w2sE[HID * INN];
    __shared__ float ys[8][32];
    __shared__ float hsv[8][128];
    int tid = threadIdx.x;
    for (int i = tid; i < INN * HID; i += 256) w1s[i] = We1[i];
    for (int i = tid; i < HID * INN; i += 256) w2sE[i] = We2[i];
    __syncthreads();

    int r = tid >> 5, lane = tid & 31;
    int b = blockIdx.x * 8 + r;
    float y = g_y[b * 32 + lane];
    float be1r[4];
#pragma unroll
    for (int k = 0; k < 4; k++) be1r[k] = be1[k * 32 + lane];
    float be2r = be2[lane];
    const float hstep = 0.5f;

    auto ev = [&](float yin) -> float {
        ys[r][lane] = yin;
        __syncwarp();
        float h0 = be1r[0], h1 = be1r[1], h2 = be1r[2], h3 = be1r[3];
#pragma unroll
        for (int i = 0; i < 32; i++) {
            float yi = ys[r][i];
            h0 += yi * w1s[i * 128 + lane];
            h1 += yi * w1s[i * 128 + 32 + lane];
            h2 += yi * w1s[i * 128 + 64 + lane];
            h3 += yi * w1s[i * 128 + 96 + lane];
        }
        hsv[r][lane]      = fast_tanh(h0);
        hsv[r][lane + 32] = fast_tanh(h1);
        hsv[r][lane + 64] = fast_tanh(h2);
        hsv[r][lane + 96] = fast_tanh(h3);
        __syncwarp();
        float o = be2r;
#pragma unroll
        for (int j = 0; j < 128; j++) o += hsv[r][j] * w2sE[j * 32 + lane];
        __syncwarp();
        return o;
    };

    for (int s = 0; s < 10; s++) {
        float k1 = ev(y);
        float k2 = ev(y + 0.25f * k1);
        float k3 = ev(y + 0.25f * k2);
        float k4 = ev(y + 0.5f  * k3);
        y += (hstep / 6.0f) * (k1 + 2.0f * k2 + 2.0f * k3 + k4);
    }
    out[b * 32 + lane] = y;
}

// ---------------- host ------------------------------------------------------
extern "C" void kernel_launch(void* const* d_in, const int* in_sizes, int n_in,
                              void* d_out, int out_size) {
    const float* coeffs = (const float*)d_in[0];
    const float* W_init = (const float*)d_in[1];
    const float* b_init = (const float*)d_in[2];
    const float* W1     = (const float*)d_in[3];
    const float* b1     = (const float*)d_in[4];
    const float* W2     = (const float*)d_in[5];
    const float* b2     = (const float*)d_in[6];
    const float* W_ro   = (const float*)d_in[7];
    const float* b_ro   = (const float*)d_in[8];
    const float* We1    = (const float*)d_in[9];
    const float* be1    = (const float*)d_in[10];
    const float* We2    = (const float*)d_in[11];
    const float* be2    = (const float*)d_in[12];
    float* out = (float*)d_out;

    cudaFuncSetAttribute(k_gemm2, cudaFuncAttributeMaxDynamicSharedMemorySize, SMEMT);

    k_prep<<<2048, 256>>>(W2);
    k_init<<<(BN * HID) / 256, 256>>>(coeffs, W_init, b_init);

    dim3 gg(16, 64);
    for (int s = 0; s < NSEG; s++) {
        int zf = s & 1;
        k_hact<<<128, 256>>>(W1, b1, coeffs, s, 1.0f, 0.0f, 0.0f, 0.0f, 0, zf);
        k_gemm2<<<gg, 256, SMEMT>>>(b2, 0, zf);
        k_hact<<<128, 256>>>(W1, b1, coeffs, s, 1.0f, 1.0f, 0.75f, 0.5f, 1, zf);
        k_gemm2<<<gg, 256, SMEMT>>>(b2, 1, zf);
        k_hact<<<128, 256>>>(W1, b1, coeffs, s, 1.0f, 1.0f, 0.75f, 0.5f, 2, zf);
        k_gemm2<<<gg, 256, SMEMT>>>(b2, 2, zf);
        int   seg4 = (s < NSEG - 1) ? s + 1 : NSEG - 1;
        float wc4  = (s < NSEG - 1) ? 0.0f : 2.0f;
        float wd4  = (s < NSEG - 1) ? 0.0f : 3.0f;
        k_hact<<<128, 256>>>(W1, b1, coeffs, seg4, 1.0f, wc4, wd4, 1.0f, 3, zf);
        k_gemm2<<<gg, 256, SMEMT>>>(b2, 3, zf);
    }

    k_readout<<<(BN * OUTN) / 256, 256>>>(W_ro, b_ro);
    k_evolve<<<BN / 8, 256>>>(We1, be1, We2, be2, out);
}

// round 15
// speedup vs baseline: 5.0571x; 1.0584x over previous
#include <cuda_runtime.h>
#include <cuda_bf16.h>
#include <stdint.h>

#define BN   2048
#define HID  128
#define INN  32
#define OUTN 32
#define NSEG 63

// ---------------- device scratch -------------------------------------------
__device__ float g_zbuf[2][BN * HID];
__device__ float g_kbuf[2][BN * HID];
__device__ float g_kacc[BN * HID];
__device__ float g_dx[BN * INN];             // per-stage dX(t), row-major
__device__ float g_y[BN * OUTN];
__device__ __nv_bfloat16 g_h0[BN * HID];     // hact split 0, row-major [row][k]
__device__ __nv_bfloat16 g_h1[BN * HID];     // hact split 1
__device__ __nv_bfloat16 g_wf0[4096 * 128];  // W2 split 0, B-fragment order
__device__ __nv_bfloat16 g_wf1[4096 * 128];  // W2 split 1

// ---------------- helpers ---------------------------------------------------
__device__ __forceinline__ float fast_tanh(float x) {
    float ax = fabsf(x);
    float e  = __expf(-2.0f * ax);
    float r  = __fdividef(1.0f - e, 1.0f + e);
    return copysignf(r, x);
}
__device__ __forceinline__ void cp16(void* sdst, const void* gsrc) {
    unsigned s = (unsigned)__cvta_generic_to_shared(sdst);
    asm volatile("cp.async.cg.shared.global [%0], [%1], 16;" :: "r"(s), "l"(gsrc));
}
#define CP_COMMIT() asm volatile("cp.async.commit_group;" ::: "memory")
#define CP_WAIT0()  asm volatile("cp.async.wait_group 0;"  ::: "memory")
#define CP_WAIT1()  asm volatile("cp.async.wait_group 1;"  ::: "memory")

__device__ __forceinline__ void mma16816(float* d, const uint32_t* a, const uint32_t* b) {
    asm volatile(
        "mma.sync.aligned.m16n8k16.row.col.f32.bf16.bf16.f32 "
        "{%0,%1,%2,%3}, {%4,%5,%6,%7}, {%8,%9}, {%0,%1,%2,%3};"
        : "+f"(d[0]), "+f"(d[1]), "+f"(d[2]), "+f"(d[3])
        : "r"(a[0]), "r"(a[1]), "r"(a[2]), "r"(a[3]), "r"(b[0]), "r"(b[1]));
}
__device__ __forceinline__ void ldmatrix_x4(uint32_t* r, uint32_t saddr) {
    asm volatile("ldmatrix.sync.aligned.m8n8.x4.shared.b16 {%0,%1,%2,%3}, [%4];"
        : "=r"(r[0]), "=r"(r[1]), "=r"(r[2]), "=r"(r[3]) : "r"(saddr));
}

// ---------------- one-time: W2 bf16 splits in B-fragment order --------------
// Layout: [ntile(512)][ktile(8)][lane(32)][4 bf16]
__global__ void k_prep(const float* __restrict__ W2) {
    int idx = blockIdx.x * 256 + threadIdx.x;   // 524288 = 128k * 4096n
    int k = idx >> 12;
    int n = idx & 4095;
    float w = W2[(long)k * 4096 + n];
    __nv_bfloat16 w0 = __float2bfloat16(w);
    __nv_bfloat16 w1 = __float2bfloat16(w - __bfloat162float(w0));
    int nt = n >> 3, kt = k >> 4;
    int t  = ((n & 7) << 2) | ((k >> 1) & 3);
    int r  = (k >> 3) & 1, hh = k & 1;
    uint32_t pos = ((uint32_t)((nt * 8 + kt) * 32 + t) << 2) + (r << 1) + hh;
    g_wf0[pos] = w0;
    g_wf1[pos] = w1;
}

// ---------------- init: z0 = a[:,0] @ W_init + b_init ----------------------
__global__ void k_init(const float* __restrict__ coeffs,
                       const float* __restrict__ W_init,
                       const float* __restrict__ b_init) {
    int idx = blockIdx.x * blockDim.x + threadIdx.x;
    int b = idx >> 7, c = idx & 127;
    const float* a0 = coeffs + (long)b * NSEG * 128;
    float acc = b_init[c];
#pragma unroll
    for (int i = 0; i < INN; i++) acc += a0[i] * W_init[i * HID + c];
    g_zbuf[0][idx] = acc;
}

// ---------------- per-stage: hact splits + dX (256 CTAs x 8 rows) ----------
__global__ void __launch_bounds__(256) k_hact(const float* __restrict__ W1,
                                              const float* __restrict__ b1,
                                              const float* __restrict__ coeffs,
                                              int seg, float wb, float wc, float wd,
                                              float alpha, int stage, int zflip) {
    __shared__ float zs[8 * 128];
    const int tid = threadIdx.x;
    const int b0  = blockIdx.x * 8;
    const float* zin = g_zbuf[zflip];
    const float* kin = (stage == 2) ? g_kbuf[1] : g_kbuf[0];

    {   // 256 float4 = 8 rows x 128
        int r = tid >> 5, m4 = tid & 31;
        float4 v = *(const float4*)&zin[(b0 + r) * 128 + m4 * 4];
        if (stage != 0) {
            float4 kv = *(const float4*)&kin[(b0 + r) * 128 + m4 * 4];
            v.x += alpha * kv.x; v.y += alpha * kv.y;
            v.z += alpha * kv.z; v.w += alpha * kv.w;
        }
        *(float4*)&zs[r * 128 + m4 * 4] = v;
    }
    {   // dX: 8 rows x 32 i = 256
        int r = tid >> 5, i = tid & 31;
        const float* cf = coeffs + ((long)(b0 + r) * NSEG + seg) * 128;
        g_dx[(b0 + r) * 32 + i] = wb * cf[32 + i] + wc * cf[64 + i] + wd * cf[96 + i];
    }
    __syncthreads();

    int c = tid & 127, half = tid >> 7;      // rows half*4 .. half*4+3
    float a4[4] = {0.f, 0.f, 0.f, 0.f};
    for (int k4 = 0; k4 < 128; k4 += 4) {
        float w0  = W1[(k4 + 0) * 128 + c];
        float w1v = W1[(k4 + 1) * 128 + c];
        float w2v = W1[(k4 + 2) * 128 + c];
        float w3v = W1[(k4 + 3) * 128 + c];
#pragma unroll
        for (int r = 0; r < 4; r++) {
            float4 zv = *(const float4*)&zs[(half * 4 + r) * 128 + k4];
            a4[r] = fmaf(zv.x, w0, fmaf(zv.y, w1v, fmaf(zv.z, w2v, fmaf(zv.w, w3v, a4[r]))));
        }
    }
    float bb1 = b1[c];
#pragma unroll
    for (int r = 0; r < 4; r++) {
        int rowg = b0 + half * 4 + r;
        float h = fmaxf(a4[r] + bb1, 0.0f);
        __nv_bfloat16 h0 = __float2bfloat16(h);
        __nv_bfloat16 h1 = __float2bfloat16(h - __bfloat162float(h0));
        g_h0[rowg * 128 + c] = h0;
        g_h1[rowg * 128 + c] = h1;
    }
}

// ---------------- per-stage: HMMA GEMM2 + tanh + contraction + RK4 ---------
// CTA: 128 rows x 64 cols. 8 warps = 4(m) x 2(n). Warp tile: 32m x 32n.
// Grid (16, 64). A via cp.async (k-half groups) + ldmatrix; B via direct LDG
// with 1-ktile register prefetch; dxT filled before mainloop; 3 split passes.
#define SA0   0                              // 128*272 = 34816
#define SA1   34816                          // -> 69632
#define SDXT  69632                          // dxT[32][132] f32 = 16896 -> 86528
#define SKST  86528                          // kst[128][2] f32 = 1024
#define SB2   87552                          // b2s[64] = 256
#define SMEMT 87808

__global__ void __launch_bounds__(256, 2) k_gemm2(
    const float* __restrict__ b2, int stage, int zflip)
{
    extern __shared__ __align__(16) char sm[];
    float* dxT = (float*)(sm + SDXT);        // [i][row] stride 132
    float* kst = (float*)(sm + SKST);        // [row][2]
    float* b2s = (float*)(sm + SB2);
    const uint32_t smb = (uint32_t)__cvta_generic_to_shared(sm);

    const int tid  = threadIdx.x;
    const int band = blockIdx.x;             // 0..15
    const int ct   = blockIdx.y;             // 0..63
    const int lane = tid & 31, wid = tid >> 5;
    const int wm = wid & 3, wn = wid >> 2;   // 4(m) x 2(n)
    const int g = lane >> 2, tq = lane & 3;

    // ---- cp.async A: group0 = k-half0 (both splits), group1 = k-half1 ----
    {
        const char* s0 = (const char*)g_h0 + (size_t)(band * 128) * 256;
        const char* s1 = (const char*)g_h1 + (size_t)(band * 128) * 256;
#pragma unroll
        for (int q = 0; q < 4; q++) {
            int id = tid + q * 256;          // 1024: row = id>>3, off 0..7
            int row = id >> 3, off = id & 7;
            cp16(sm + SA0 + row * 272 + off * 16, s0 + row * 256 + off * 16);
            cp16(sm + SA1 + row * 272 + off * 16, s1 + row * 256 + off * 16);
        }
        CP_COMMIT();
#pragma unroll
        for (int q = 0; q < 4; q++) {
            int id = tid + q * 256;
            int row = id >> 3, off = (id & 7) + 8;   // offs 8..15
            cp16(sm + SA0 + row * 272 + off * 16, s0 + row * 256 + off * 16);
            cp16(sm + SA1 + row * 272 + off * 16, s1 + row * 256 + off * 16);
        }
        CP_COMMIT();
    }

    // ---- dxT fill (overlaps A cp.async) + bias ----
    {
        const float* dxg = g_dx + (size_t)(band * 128) * 32;
#pragma unroll
        for (int q = 0; q < 16; q++) {
            int e = tid + q * 256;           // 4096 = 128 rows x 32 i
            int row = e >> 5, i = e & 31;
            dxT[i * 132 + row] = dxg[row * 32 + i];
        }
    }
    if (tid < 64) b2s[tid] = b2[ct * 64 + tid];

    // ---- mainloop: B direct LDG with 1-ktile prefetch --------------------
    float acc[2][4][4];
#pragma unroll
    for (int mt = 0; mt < 2; mt++)
#pragma unroll
        for (int nt = 0; nt < 4; nt++)
#pragma unroll
            for (int r = 0; r < 4; r++) acc[mt][nt][r] = 0.0f;

    const uint2* B0 = (const uint2*)g_wf0;
    const uint2* B1 = (const uint2*)g_wf1;
    const uint32_t bbase = (uint32_t)(ct * 8 + wn * 4) * 8;   // ntile*8 (+kt)

    uint2 c0[4], c1[4], n0[4], n1[4];
#pragma unroll
    for (int nt = 0; nt < 4; nt++) {
        uint32_t fo = (bbase + nt * 8 + 0) * 32 + lane;
        c0[nt] = __ldg(&B0[fo]);
        c1[nt] = __ldg(&B1[fo]);
    }

    const int lrow = lane & 15, lcol = lane >> 4;
#pragma unroll
    for (int kt = 0; kt < 8; kt++) {
        if (kt == 0) { CP_WAIT1(); __syncthreads(); }   // A half0 ready
        if (kt == 4) { CP_WAIT0(); __syncthreads(); }   // A half1 ready
        if (kt < 7) {
#pragma unroll
            for (int nt = 0; nt < 4; nt++) {
                uint32_t fo = (bbase + nt * 8 + kt + 1) * 32 + lane;
                n0[nt] = __ldg(&B0[fo]);
                n1[nt] = __ldg(&B1[fo]);
            }
        }
        uint32_t afr0[2][4], afr1[2][4];
#pragma unroll
        for (int mt = 0; mt < 2; mt++) {
            uint32_t ad = smb + SA0 + (uint32_t)(wm * 32 + mt * 16 + lrow) * 272
                        + kt * 32 + lcol * 16;
            ldmatrix_x4(afr0[mt], ad);
            ldmatrix_x4(afr1[mt], ad + 34816);
        }
#pragma unroll
        for (int nt = 0; nt < 4; nt++) {
#pragma unroll
            for (int mt = 0; mt < 2; mt++) {
                mma16816(acc[mt][nt], afr0[mt], (const uint32_t*)&c0[nt]);  // h0*w0
                mma16816(acc[mt][nt], afr0[mt], (const uint32_t*)&c1[nt]);  // h0*w1
                mma16816(acc[mt][nt], afr1[mt], (const uint32_t*)&c0[nt]);  // h1*w0
            }
        }
#pragma unroll
        for (int nt = 0; nt < 4; nt++) { c0[nt] = n0[nt]; c1[nt] = n1[nt]; }
    }

    // ---- epilogue: bias + tanh + dX contraction --------------------------
    // acc[mt][nt][r]: row = wm*32+mt*16+g+(r>>1)*8 ; col = wn*32+nt*8+tq*2+(r&1)
    float part[2][2] = {{0.f, 0.f}, {0.f, 0.f}};
#pragma unroll
    for (int mt = 0; mt < 2; mt++)
#pragma unroll
        for (int nt = 0; nt < 4; nt++)
#pragma unroll
            for (int r = 0; r < 4; r++) {
                int i   = nt * 8 + tq * 2 + (r & 1);
                int col = wn * 32 + i;
                int row = wm * 32 + mt * 16 + g + ((r >> 1) << 3);
                float t = fast_tanh(acc[mt][nt][r] + b2s[col]);
                part[mt][r >> 1] += t * dxT[i * 132 + row];
            }
#pragma unroll
    for (int mt = 0; mt < 2; mt++)
#pragma unroll
        for (int p = 0; p < 2; p++) {
            float v = part[mt][p];
            v += __shfl_xor_sync(0xffffffffu, v, 1);
            v += __shfl_xor_sync(0xffffffffu, v, 2);
            part[mt][p] = v;
        }
    if (tq == 0) {
#pragma unroll
        for (int mt = 0; mt < 2; mt++)
#pragma unroll
            for (int p = 0; p < 2; p++) {
                int row = wm * 32 + mt * 16 + g + p * 8;
                kst[row * 2 + wn] = part[mt][p];
            }
    }
    __syncthreads();

    // ---- RK4 bookkeeping: 128 rows x 2 h -> float2 -----------------------
    if (tid < 128) {
        int row = tid;
        float2 kv = *(float2*)&kst[row * 2];
        int gi = (band * 128 + row) * 128 + ct * 2;
        float* kout = (stage == 1) ? g_kbuf[1] : g_kbuf[0];
        if (stage == 0) {
            *(float2*)&kout[gi] = kv;
            *(float2*)&g_kacc[gi] = kv;
        } else if (stage == 3) {
            float2 ka = *(float2*)&g_kacc[gi];
            float2 zi = *(float2*)&g_zbuf[zflip][gi];
            float2 zo;
            zo.x = zi.x + (ka.x + kv.x) * (1.0f / 6.0f);
            zo.y = zi.y + (ka.y + kv.y) * (1.0f / 6.0f);
            *(float2*)&g_zbuf[zflip ^ 1][gi] = zo;
        } else {
            *(float2*)&kout[gi] = kv;
            float2 ka = *(float2*)&g_kacc[gi];
            ka.x += 2.0f * kv.x; ka.y += 2.0f * kv.y;
            *(float2*)&g_kacc[gi] = ka;
        }
    }
}

// ---------------- readout ---------------------------------------------------
__global__ void k_readout(const float* __restrict__ W_ro,
                          const float* __restrict__ b_ro) {
    int idx = blockIdx.x * blockDim.x + threadIdx.x;
    int b = idx >> 5, o = idx & 31;
    const float* zr = g_zbuf[1] + b * 128;   // NSEG odd -> final z in buf 1
    float acc = b_ro[o];
#pragma unroll
    for (int h = 0; h < 128; h++) acc += zr[h] * W_ro[h * 32 + o];
    g_y[idx] = acc;
}

// ---------------- evolve ----------------------------------------------------
__global__ void __launch_bounds__(256) k_evolve(const float* __restrict__ We1,
                                                const float* __restrict__ be1,
                                                const float* __restrict__ We2,
                                                const float* __restrict__ be2,
                                                float* __restrict__ out) {
    __shared__ float w1s[INN * HID];
    __shared__ float w2sE[HID * INN];
    __shared__ float ys[8][32];
    __shared__ float hsv[8][128];
    int tid = threadIdx.x;
    for (int i = tid; i < INN * HID; i += 256) w1s[i] = We1[i];
    for (int i = tid; i < HID * INN; i += 256) w2sE[i] = We2[i];
    __syncthreads();

    int r = tid >> 5, lane = tid & 31;
    int b = blockIdx.x * 8 + r;
    float y = g_y[b * 32 + lane];
    float be1r[4];
#pragma unroll
    for (int k = 0; k < 4; k++) be1r[k] = be1[k * 32 + lane];
    float be2r = be2[lane];
    const float hstep = 0.5f;

    auto ev = [&](float yin) -> float {
        ys[r][lane] = yin;
        __syncwarp();
        float h0 = be1r[0], h1 = be1r[1], h2 = be1r[2], h3 = be1r[3];
#pragma unroll
        for (int i = 0; i < 32; i++) {
            float yi = ys[r][i];
            h0 += yi * w1s[i * 128 + lane];
            h1 += yi * w1s[i * 128 + 32 + lane];
            h2 += yi * w1s[i * 128 + 64 + lane];
            h3 += yi * w1s[i * 128 + 96 + lane];
        }
        hsv[r][lane]      = fast_tanh(h0);
        hsv[r][lane + 32] = fast_tanh(h1);
        hsv[r][lane + 64] = fast_tanh(h2);
        hsv[r][lane + 96] = fast_tanh(h3);
        __syncwarp();
        float o = be2r;
#pragma unroll
        for (int j = 0; j < 128; j++) o += hsv[r][j] * w2sE[j * 32 + lane];
        __syncwarp();
        return o;
    };

    for (int s = 0; s < 10; s++) {
        float k1 = ev(y);
        float k2 = ev(y + 0.25f * k1);
        float k3 = ev(y + 0.25f * k2);
        float k4 = ev(y + 0.5f  * k3);
        y += (hstep / 6.0f) * (k1 + 2.0f * k2 + 2.0f * k3 + k4);
    }
    out[b * 32 + lane] = y;
}

// ---------------- host ------------------------------------------------------
extern "C" void kernel_launch(void* const* d_in, const int* in_sizes, int n_in,
                              void* d_out, int out_size) {
    const float* coeffs = (const float*)d_in[0];
    const float* W_init = (const float*)d_in[1];
    const float* b_init = (const float*)d_in[2];
    const float* W1     = (const float*)d_in[3];
    const float* b1     = (const float*)d_in[4];
    const float* W2     = (const float*)d_in[5];
    const float* b2     = (const float*)d_in[6];
    const float* W_ro   = (const float*)d_in[7];
    const float* b_ro   = (const float*)d_in[8];
    const float* We1    = (const float*)d_in[9];
    const float* be1    = (const float*)d_in[10];
    const float* We2    = (const float*)d_in[11];
    const float* be2    = (const float*)d_in[12];
    float* out = (float*)d_out;

    cudaFuncSetAttribute(k_gemm2, cudaFuncAttributeMaxDynamicSharedMemorySize, SMEMT);

    k_prep<<<2048, 256>>>(W2);
    k_init<<<(BN * HID) / 256, 256>>>(coeffs, W_init, b_init);

    dim3 gg(16, 64);
    for (int s = 0; s < NSEG; s++) {
        int zf = s & 1;
        k_hact<<<256, 256>>>(W1, b1, coeffs, s, 1.0f, 0.0f, 0.0f, 0.0f, 0, zf);
        k_gemm2<<<gg, 256, SMEMT>>>(b2, 0, zf);
        k_hact<<<256, 256>>>(W1, b1, coeffs, s, 1.0f, 1.0f, 0.75f, 0.5f, 1, zf);
        k_gemm2<<<gg, 256, SMEMT>>>(b2, 1, zf);
        k_hact<<<256, 256>>>(W1, b1, coeffs, s, 1.0f, 1.0f, 0.75f, 0.5f, 2, zf);
        k_gemm2<<<gg, 256, SMEMT>>>(b2, 2, zf);
        int   seg4 = (s < NSEG - 1) ? s + 1 : NSEG - 1;
        float wc4  = (s < NSEG - 1) ? 0.0f : 2.0f;
        float wd4  = (s < NSEG - 1) ? 0.0f : 3.0f;
        k_hact<<<256, 256>>>(W1, b1, coeffs, seg4, 1.0f, wc4, wd4, 1.0f, 3, zf);
        k_gemm2<<<gg, 256, SMEMT>>>(b2, 3, zf);
    }

    k_readout<<<(BN * OUTN) / 256, 256>>>(W_ro, b_ro);
    k_evolve<<<BN / 8, 256>>>(We1, be1, We2, be2, out);
}

// round 17
// speedup vs baseline: 5.2763x; 1.0434x over previous
#include <cuda_runtime.h>
#include <cuda_bf16.h>
#include <stdint.h>

#define BN   2048
#define HID  128
#define INN  32
#define OUTN 32
#define NSEG 63

// ---------------- device scratch -------------------------------------------
__device__ float g_zbuf[2][BN * HID];
__device__ float g_kbuf[2][BN * HID];
__device__ float g_kacc[BN * HID];
__device__ float g_dx[BN * INN];             // per-stage dX(t), row-major
__device__ float g_y[BN * OUTN];
__device__ __nv_bfloat16 g_h0[BN * HID];     // hact split 0, row-major [row][k]
__device__ __nv_bfloat16 g_h1[BN * HID];     // hact split 1
__device__ __nv_bfloat16 g_wf0[4096 * 128];  // W2 split 0, B-fragment order
__device__ __nv_bfloat16 g_wf1[4096 * 128];  // W2 split 1

// ---------------- helpers ---------------------------------------------------
__device__ __forceinline__ float fast_tanh(float x) {
    float ax = fabsf(x);
    float e  = __expf(-2.0f * ax);
    float r  = __fdividef(1.0f - e, 1.0f + e);
    return copysignf(r, x);
}
__device__ __forceinline__ void cp16(void* sdst, const void* gsrc) {
    unsigned s = (unsigned)__cvta_generic_to_shared(sdst);
    asm volatile("cp.async.cg.shared.global [%0], [%1], 16;" :: "r"(s), "l"(gsrc));
}
#define CP_COMMIT() asm volatile("cp.async.commit_group;" ::: "memory")
#define CP_WAIT0()  asm volatile("cp.async.wait_group 0;"  ::: "memory")
#define CP_WAIT1()  asm volatile("cp.async.wait_group 1;"  ::: "memory")

__device__ __forceinline__ void mma16816(float* d, const uint32_t* a, const uint32_t* b) {
    asm volatile(
        "mma.sync.aligned.m16n8k16.row.col.f32.bf16.bf16.f32 "
        "{%0,%1,%2,%3}, {%4,%5,%6,%7}, {%8,%9}, {%0,%1,%2,%3};"
        : "+f"(d[0]), "+f"(d[1]), "+f"(d[2]), "+f"(d[3])
        : "r"(a[0]), "r"(a[1]), "r"(a[2]), "r"(a[3]), "r"(b[0]), "r"(b[1]));
}
__device__ __forceinline__ void ldmatrix_x4(uint32_t* r, uint32_t saddr) {
    asm volatile("ldmatrix.sync.aligned.m8n8.x4.shared.b16 {%0,%1,%2,%3}, [%4];"
        : "=r"(r[0]), "=r"(r[1]), "=r"(r[2]), "=r"(r[3]) : "r"(saddr));
}

// ---------------- one-time: W2 bf16 splits in B-fragment order --------------
// Layout: [ntile(512)][ktile(8)][lane(32)][4 bf16]
__global__ void k_prep(const float* __restrict__ W2) {
    int idx = blockIdx.x * 256 + threadIdx.x;   // 524288 = 128k * 4096n
    int k = idx >> 12;
    int n = idx & 4095;
    float w = W2[(long)k * 4096 + n];
    __nv_bfloat16 w0 = __float2bfloat16(w);
    __nv_bfloat16 w1 = __float2bfloat16(w - __bfloat162float(w0));
    int nt = n >> 3, kt = k >> 4;
    int t  = ((n & 7) << 2) | ((k >> 1) & 3);
    int r  = (k >> 3) & 1, hh = k & 1;
    uint32_t pos = ((uint32_t)((nt * 8 + kt) * 32 + t) << 2) + (r << 1) + hh;
    g_wf0[pos] = w0;
    g_wf1[pos] = w1;
}

// ---------------- init: z0 = a[:,0] @ W_init + b_init ----------------------
__global__ void k_init(const float* __restrict__ coeffs,
                       const float* __restrict__ W_init,
                       const float* __restrict__ b_init) {
    int idx = blockIdx.x * blockDim.x + threadIdx.x;
    int b = idx >> 7, c = idx & 127;
    const float* a0 = coeffs + (long)b * NSEG * 128;
    float acc = b_init[c];
#pragma unroll
    for (int i = 0; i < INN; i++) acc += a0[i] * W_init[i * HID + c];
    g_zbuf[0][idx] = acc;
}

// ---------------- per-stage: hact splits + dX (256 CTAs x 8 rows) ----------
__global__ void __launch_bounds__(256) k_hact(const float* __restrict__ W1,
                                              const float* __restrict__ b1,
                                              const float* __restrict__ coeffs,
                                              int seg, float wb, float wc, float wd,
                                              float alpha, int stage, int zflip) {
    __shared__ float zs[8 * 128];
    const int tid = threadIdx.x;
    const int b0  = blockIdx.x * 8;
    const float* zin = g_zbuf[zflip];
    const float* kin = (stage == 2) ? g_kbuf[1] : g_kbuf[0];

    {   // 256 float4 = 8 rows x 128
        int r = tid >> 5, m4 = tid & 31;
        float4 v = *(const float4*)&zin[(b0 + r) * 128 + m4 * 4];
        if (stage != 0) {
            float4 kv = *(const float4*)&kin[(b0 + r) * 128 + m4 * 4];
            v.x += alpha * kv.x; v.y += alpha * kv.y;
            v.z += alpha * kv.z; v.w += alpha * kv.w;
        }
        *(float4*)&zs[r * 128 + m4 * 4] = v;
    }
    {   // dX: 8 rows x 32 i = 256
        int r = tid >> 5, i = tid & 31;
        const float* cf = coeffs + ((long)(b0 + r) * NSEG + seg) * 128;
        g_dx[(b0 + r) * 32 + i] = wb * cf[32 + i] + wc * cf[64 + i] + wd * cf[96 + i];
    }
    __syncthreads();

    int c = tid & 127, half = tid >> 7;      // rows half*4 .. half*4+3
    float a4[4] = {0.f, 0.f, 0.f, 0.f};
    for (int k4 = 0; k4 < 128; k4 += 4) {
        float w0  = W1[(k4 + 0) * 128 + c];
        float w1v = W1[(k4 + 1) * 128 + c];
        float w2v = W1[(k4 + 2) * 128 + c];
        float w3v = W1[(k4 + 3) * 128 + c];
#pragma unroll
        for (int r = 0; r < 4; r++) {
            float4 zv = *(const float4*)&zs[(half * 4 + r) * 128 + k4];
            a4[r] = fmaf(zv.x, w0, fmaf(zv.y, w1v, fmaf(zv.z, w2v, fmaf(zv.w, w3v, a4[r]))));
        }
    }
    float bb1 = b1[c];
#pragma unroll
    for (int r = 0; r < 4; r++) {
        int rowg = b0 + half * 4 + r;
        float h = fmaxf(a4[r] + bb1, 0.0f);
        __nv_bfloat16 h0 = __float2bfloat16(h);
        __nv_bfloat16 h1 = __float2bfloat16(h - __bfloat162float(h0));
        g_h0[rowg * 128 + c] = h0;
        g_h1[rowg * 128 + c] = h1;
    }
}

// ---------------- per-stage: HMMA GEMM2 + tanh + contraction + RK4 ---------
// CTA: 128 rows x 256 cols (4 subtiles of 64 cols). 8 warps = 4(m) x 2(n).
// Grid (16, 16) = 256 CTAs = one co-resident wave. A staged once per CTA;
// B via direct LDG with cross-subtile register prefetch; 3 split passes.
#define NSUB  4
#define SA0   0                              // 128*272 = 34816
#define SA1   34816                          // -> 69632
#define SDXT  69632                          // dxT[32][132] f32 = 16896 -> 86528
#define SKST  86528                          // kst[128][2] f32 = 1024
#define SB2   87552                          // b2s[256] = 1024
#define SMEMT 88576

__global__ void __launch_bounds__(256, 2) k_gemm2(
    const float* __restrict__ b2, int stage, int zflip)
{
    extern __shared__ __align__(16) char sm[];
    float* dxT = (float*)(sm + SDXT);        // [i][row] stride 132
    float* kst = (float*)(sm + SKST);        // [row][2]
    float* b2s = (float*)(sm + SB2);
    const uint32_t smb = (uint32_t)__cvta_generic_to_shared(sm);

    const int tid  = threadIdx.x;
    const int band = blockIdx.x;             // 0..15
    const int cg   = blockIdx.y;             // 0..15 (256-col group)
    const int lane = tid & 31, wid = tid >> 5;
    const int wm = wid & 3, wn = wid >> 2;   // 4(m) x 2(n)
    const int g = lane >> 2, tq = lane & 3;

    // ---- cp.async A: group0 = k-half0 (both splits), group1 = k-half1 ----
    {
        const char* s0 = (const char*)g_h0 + (size_t)(band * 128) * 256;
        const char* s1 = (const char*)g_h1 + (size_t)(band * 128) * 256;
#pragma unroll
        for (int q = 0; q < 4; q++) {
            int id = tid + q * 256;          // 1024: row = id>>3, off 0..7
            int row = id >> 3, off = id & 7;
            cp16(sm + SA0 + row * 272 + off * 16, s0 + row * 256 + off * 16);
            cp16(sm + SA1 + row * 272 + off * 16, s1 + row * 256 + off * 16);
        }
        CP_COMMIT();
#pragma unroll
        for (int q = 0; q < 4; q++) {
            int id = tid + q * 256;
            int row = id >> 3, off = (id & 7) + 8;   // offs 8..15
            cp16(sm + SA0 + row * 272 + off * 16, s0 + row * 256 + off * 16);
            cp16(sm + SA1 + row * 272 + off * 16, s1 + row * 256 + off * 16);
        }
        CP_COMMIT();
    }

    // ---- dxT fill (overlaps A cp.async) + bias for all 4 subtiles ----
    {
        const float* dxg = g_dx + (size_t)(band * 128) * 32;
#pragma unroll
        for (int q = 0; q < 16; q++) {
            int e = tid + q * 256;           // 4096 = 128 rows x 32 i
            int row = e >> 5, i = e & 31;
            dxT[i * 132 + row] = dxg[row * 32 + i];
        }
    }
    b2s[tid] = b2[cg * 256 + tid];

    const uint2* B0 = (const uint2*)g_wf0;
    const uint2* B1 = (const uint2*)g_wf1;
    const int lrow = lane & 15, lcol = lane >> 4;

    uint2 c0[4], c1[4], n0[4], n1[4];
    {   // preload B for subtile 0, kt 0
        uint32_t bb = (uint32_t)((cg * 4) * 8 + wn * 4) * 8;
#pragma unroll
        for (int nt = 0; nt < 4; nt++) {
            uint32_t fo = (bb + nt * 8) * 32 + lane;
            c0[nt] = __ldg(&B0[fo]);
            c1[nt] = __ldg(&B1[fo]);
        }
    }

    float* kout = (stage == 1) ? g_kbuf[1] : g_kbuf[0];

#pragma unroll 1
    for (int sub = 0; sub < NSUB; sub++) {
        const int ctile = cg * 4 + sub;      // 0..63
        const uint32_t bbase = (uint32_t)(ctile * 8 + wn * 4) * 8;

        float acc[2][4][4];
#pragma unroll
        for (int mt = 0; mt < 2; mt++)
#pragma unroll
            for (int nt = 0; nt < 4; nt++)
#pragma unroll
                for (int r = 0; r < 4; r++) acc[mt][nt][r] = 0.0f;

#pragma unroll
        for (int kt = 0; kt < 8; kt++) {
            if (sub == 0 && kt == 0) { CP_WAIT1(); __syncthreads(); }  // A half0
            if (sub == 0 && kt == 4) { CP_WAIT0(); __syncthreads(); }  // A half1
            // prefetch next B fragment set (next kt, or next subtile's kt0)
            if (kt < 7) {
#pragma unroll
                for (int nt = 0; nt < 4; nt++) {
                    uint32_t fo = (bbase + nt * 8 + kt + 1) * 32 + lane;
                    n0[nt] = __ldg(&B0[fo]);
                    n1[nt] = __ldg(&B1[fo]);
                }
            } else if (sub < NSUB - 1) {
                uint32_t bb2 = (uint32_t)((ctile + 1) * 8 + wn * 4) * 8;
#pragma unroll
                for (int nt = 0; nt < 4; nt++) {
                    uint32_t fo = (bb2 + nt * 8) * 32 + lane;
                    n0[nt] = __ldg(&B0[fo]);
                    n1[nt] = __ldg(&B1[fo]);
                }
            }
            uint32_t afr0[2][4], afr1[2][4];
#pragma unroll
            for (int mt = 0; mt < 2; mt++) {
                uint32_t ad = smb + SA0 + (uint32_t)(wm * 32 + mt * 16 + lrow) * 272
                            + kt * 32 + lcol * 16;
                ldmatrix_x4(afr0[mt], ad);
                ldmatrix_x4(afr1[mt], ad + 34816);
            }
#pragma unroll
            for (int nt = 0; nt < 4; nt++) {
#pragma unroll
                for (int mt = 0; mt < 2; mt++) {
                    mma16816(acc[mt][nt], afr0[mt], (const uint32_t*)&c0[nt]);  // h0*w0
                    mma16816(acc[mt][nt], afr0[mt], (const uint32_t*)&c1[nt]);  // h0*w1
                    mma16816(acc[mt][nt], afr1[mt], (const uint32_t*)&c0[nt]);  // h1*w0
                }
            }
#pragma unroll
            for (int nt = 0; nt < 4; nt++) { c0[nt] = n0[nt]; c1[nt] = n1[nt]; }
        }

        // ---- epilogue: bias + tanh + dX contraction ----------------------
        float part[2][2] = {{0.f, 0.f}, {0.f, 0.f}};
#pragma unroll
        for (int mt = 0; mt < 2; mt++)
#pragma unroll
            for (int nt = 0; nt < 4; nt++)
#pragma unroll
                for (int r = 0; r < 4; r++) {
                    int i   = nt * 8 + tq * 2 + (r & 1);
                    int col = sub * 64 + wn * 32 + i;
                    int row = wm * 32 + mt * 16 + g + ((r >> 1) << 3);
                    float t = fast_tanh(acc[mt][nt][r] + b2s[col]);
                    part[mt][r >> 1] += t * dxT[i * 132 + row];
                }
#pragma unroll
        for (int mt = 0; mt < 2; mt++)
#pragma unroll
            for (int p = 0; p < 2; p++) {
                float v = part[mt][p];
                v += __shfl_xor_sync(0xffffffffu, v, 1);
                v += __shfl_xor_sync(0xffffffffu, v, 2);
                part[mt][p] = v;
            }
        if (tq == 0) {
#pragma unroll
            for (int mt = 0; mt < 2; mt++)
#pragma unroll
                for (int p = 0; p < 2; p++) {
                    int row = wm * 32 + mt * 16 + g + p * 8;
                    kst[row * 2 + wn] = part[mt][p];
                }
        }
        __syncthreads();

        // ---- RK4 bookkeeping: 128 rows x 2 h -> float2 -------------------
        if (tid < 128) {
            int row = tid;
            float2 kv = *(float2*)&kst[row * 2];
            int gi = (band * 128 + row) * 128 + ctile * 2;
            if (stage == 0) {
                *(float2*)&kout[gi] = kv;
                *(float2*)&g_kacc[gi] = kv;
            } else if (stage == 3) {
                float2 ka = *(float2*)&g_kacc[gi];
                float2 zi = *(float2*)&g_zbuf[zflip][gi];
                float2 zo;
                zo.x = zi.x + (ka.x + kv.x) * (1.0f / 6.0f);
                zo.y = zi.y + (ka.y + kv.y) * (1.0f / 6.0f);
                *(float2*)&g_zbuf[zflip ^ 1][gi] = zo;
            } else {
                *(float2*)&kout[gi] = kv;
                float2 ka = *(float2*)&g_kacc[gi];
                ka.x += 2.0f * kv.x; ka.y += 2.0f * kv.y;
                *(float2*)&g_kacc[gi] = ka;
            }
        }
        __syncthreads();                     // kst safe to overwrite next sub
    }
}

// ---------------- readout ---------------------------------------------------
__global__ void k_readout(const float* __restrict__ W_ro,
                          const float* __restrict__ b_ro) {
    int idx = blockIdx.x * blockDim.x + threadIdx.x;
    int b = idx >> 5, o = idx & 31;
    const float* zr = g_zbuf[1] + b * 128;   // NSEG odd -> final z in buf 1
    float acc = b_ro[o];
#pragma unroll
    for (int h = 0; h < 128; h++) acc += zr[h] * W_ro[h * 32 + o];
    g_y[idx] = acc;
}

// ---------------- evolve ----------------------------------------------------
__global__ void __launch_bounds__(256) k_evolve(const float* __restrict__ We1,
                                                const float* __restrict__ be1,
                                                const float* __restrict__ We2,
                                                const float* __restrict__ be2,
                                                float* __restrict__ out) {
    __shared__ float w1s[INN * HID];
    __shared__ float w2sE[HID * INN];
    __shared__ float ys[8][32];
    __shared__ float hsv[8][128];
    int tid = threadIdx.x;
    for (int i = tid; i < INN * HID; i += 256) w1s[i] = We1[i];
    for (int i = tid; i < HID * INN; i += 256) w2sE[i] = We2[i];
    __syncthreads();

    int r = tid >> 5, lane = tid & 31;
    int b = blockIdx.x * 8 + r;
    float y = g_y[b * 32 + lane];
    float be1r[4];
#pragma unroll
    for (int k = 0; k < 4; k++) be1r[k] = be1[k * 32 + lane];
    float be2r = be2[lane];
    const float hstep = 0.5f;

    auto ev = [&](float yin) -> float {
        ys[r][lane] = yin;
        __syncwarp();
        float h0 = be1r[0], h1 = be1r[1], h2 = be1r[2], h3 = be1r[3];
#pragma unroll
        for (int i = 0; i < 32; i++) {
            float yi = ys[r][i];
            h0 += yi * w1s[i * 128 + lane];
            h1 += yi * w1s[i * 128 + 32 + lane];
            h2 += yi * w1s[i * 128 + 64 + lane];
            h3 += yi * w1s[i * 128 + 96 + lane];
        }
        hsv[r][lane]      = fast_tanh(h0);
        hsv[r][lane + 32] = fast_tanh(h1);
        hsv[r][lane + 64] = fast_tanh(h2);
        hsv[r][lane + 96] = fast_tanh(h3);
        __syncwarp();
        float o = be2r;
#pragma unroll
        for (int j = 0; j < 128; j++) o += hsv[r][j] * w2sE[j * 32 + lane];
        __syncwarp();
        return o;
    };

    for (int s = 0; s < 10; s++) {
        float k1 = ev(y);
        float k2 = ev(y + 0.25f * k1);
        float k3 = ev(y + 0.25f * k2);
        float k4 = ev(y + 0.5f  * k3);
        y += (hstep / 6.0f) * (k1 + 2.0f * k2 + 2.0f * k3 + k4);
    }
    out[b * 32 + lane] = y;
}

// ---------------- host ------------------------------------------------------
extern "C" void kernel_launch(void* const* d_in, const int* in_sizes, int n_in,
                              void* d_out, int out_size) {
    const float* coeffs = (const float*)d_in[0];
    const float* W_init = (const float*)d_in[1];
    const float* b_init = (const float*)d_in[2];
    const float* W1     = (const float*)d_in[3];
    const float* b1     = (const float*)d_in[4];
    const float* W2     = (const float*)d_in[5];
    const float* b2     = (const float*)d_in[6];
    const float* W_ro   = (const float*)d_in[7];
    const float* b_ro   = (const float*)d_in[8];
    const float* We1    = (const float*)d_in[9];
    const float* be1    = (const float*)d_in[10];
    const float* We2    = (const float*)d_in[11];
    const float* be2    = (const float*)d_in[12];
    float* out = (float*)d_out;

    cudaFuncSetAttribute(k_gemm2, cudaFuncAttributeMaxDynamicSharedMemorySize, SMEMT);

    k_prep<<<2048, 256>>>(W2);
    k_init<<<(BN * HID) / 256, 256>>>(coeffs, W_init, b_init);

    dim3 gg(16, 16);
    for (int s = 0; s < NSEG; s++) {
        int zf = s & 1;
        k_hact<<<256, 256>>>(W1, b1, coeffs, s, 1.0f, 0.0f, 0.0f, 0.0f, 0, zf);
        k_gemm2<<<gg, 256, SMEMT>>>(b2, 0, zf);
        k_hact<<<256, 256>>>(W1, b1, coeffs, s, 1.0f, 1.0f, 0.75f, 0.5f, 1, zf);
        k_gemm2<<<gg, 256, SMEMT>>>(b2, 1, zf);
        k_hact<<<256, 256>>>(W1, b1, coeffs, s, 1.0f, 1.0f, 0.75f, 0.5f, 2, zf);
        k_gemm2<<<gg, 256, SMEMT>>>(b2, 2, zf);
        int   seg4 = (s < NSEG - 1) ? s + 1 : NSEG - 1;
        float wc4  = (s < NSEG - 1) ? 0.0f : 2.0f;
        float wd4  = (s < NSEG - 1) ? 0.0f : 3.0f;
        k_hact<<<256, 256>>>(W1, b1, coeffs, seg4, 1.0f, wc4, wd4, 1.0f, 3, zf);
        k_gemm2<<<gg, 256, SMEMT>>>(b2, 3, zf);
    }

    k_readout<<<(BN * OUTN) / 256, 256>>>(W_ro, b_ro);
    k_evolve<<<BN / 8, 256>>>(We1, be1, We2, be2, out);
}